// round 2
// baseline (speedup 1.0000x reference)
#include <cuda_runtime.h>
#include <cuda_fp16.h>
#include <mma.h>
#include <cstdint>

using namespace nvcuda;

// ---------------- problem constants ----------------
#define N_NODES 50000
#define N_EDGES 500000
#define FD      128           // node/edge feature dim
#define KDIM    384           // GEMM K (2*FD + FD)
#define NOUT    256           // GEMM N (2*FD)
#define TILE_M  128           // edges per tile

// ---------------- smem layout (edge kernel) ----------------
#define B_LD     264          // padded halfs per W row (16B mult, conflict-shifting)
#define A_LD     72           // padded halfs per A row (chunk K=64 + 8)
#define SLAB_LD  260          // padded floats per C-slab row

#define B_OFF    0
#define B_BYTES  (KDIM * B_LD * 2)         // 202752
#define A_OFF    B_BYTES
#define A_BYTES  (TILE_M * A_LD * 2)       // 18432 (slab 16*260*4=16640 aliases this)
#define IDX_OFF  (A_OFF + A_BYTES)         // 221184 : src[128], dst[128]
#define PAR_OFF  (IDX_OFF + 1024)          // bias[256] eg[128] eb[128] floats
#define SMEM_TOTAL (PAR_OFF + 2048)        // 224256 <= 227KB

// ---------------- scratch (__device__ globals, no allocs) ----------------
__device__ __align__(256) __half g_xn16[(size_t)N_NODES * FD];
__device__ __align__(256) __half g_wt16[(size_t)KDIM * NOUT];

// =====================================================================
// Kernel 1: per-node LayerNorm -> fp16
// =====================================================================
__global__ void node_prep_kernel(const float* __restrict__ x,
                                 const float* __restrict__ ng,
                                 const float* __restrict__ nb) {
    const int n = blockIdx.x, t = threadIdx.x;
    float v = x[(size_t)n * FD + t];
    float s = v, q = v * v;
#pragma unroll
    for (int o = 16; o; o >>= 1) {
        s += __shfl_xor_sync(0xffffffffu, s, o);
        q += __shfl_xor_sync(0xffffffffu, q, o);
    }
    __shared__ float s1[4], s2[4];
    if ((t & 31) == 0) { s1[t >> 5] = s; s2[t >> 5] = q; }
    __syncthreads();
    s = s1[0] + s1[1] + s1[2] + s1[3];
    q = s2[0] + s2[1] + s2[2] + s2[3];
    const float mu  = s * (1.f / FD);
    const float var = q * (1.f / FD) - mu * mu;
    const float xn  = (v - mu) * rsqrtf(var + 1e-5f) * __ldg(ng + t) + __ldg(nb + t);
    g_xn16[(size_t)n * FD + t] = __float2half_rn(xn);
}

// =====================================================================
// Kernel 2: W [384,256] f32 -> fp16 row-major
// =====================================================================
__global__ void w_prep_kernel(const float* __restrict__ W) {
    const int i = blockIdx.x * 256 + threadIdx.x;   // 0..98303
    g_wt16[i] = __float2half_rn(W[i]);
}

// =====================================================================
// Kernel 3: fused edge GEMM (wmma/HMMA) + gated residual + LayerNorm
// persistent CTAs, W resident in SMEM, A built per K=64 chunk
// =====================================================================
__global__ void __launch_bounds__(512, 1)
edge_kernel(const int* __restrict__ ei, const float* __restrict__ ea,
            const float* __restrict__ bias, const float* __restrict__ eg,
            const float* __restrict__ eb, float* __restrict__ out) {
    extern __shared__ char smem[];
    __half* s_b  = (__half*)(smem + B_OFF);
    __half* s_a  = (__half*)(smem + A_OFF);
    float*  slab = (float*)(smem + A_OFF);    // aliases A after GEMM
    int*    s_src = (int*)(smem + IDX_OFF);
    int*    s_dst = s_src + 128;
    float*  s_bias = (float*)(smem + PAR_OFF);   // 256
    float*  s_eg   = s_bias + 256;               // 128
    float*  s_eb   = s_eg + 128;                 // 128

    const int tid  = threadIdx.x;
    const int wid  = tid >> 5;
    const int lane = tid & 31;
    const int warp_row = wid >> 2;   // 0..3 : rows [warp_row*32, +32)
    const int warp_col = wid & 3;    // 0..3 : cols [warp_col*64, +64)
    const int row4 = tid >> 2;       // 0..127 (A build row)
    const int q4   = tid & 3;        // 32B segment within row

    // ---- stage resident B (fp16, padded) + params ----
    for (int i = tid; i < KDIM * 32; i += 512) {      // 32 uint4 per row
        const int row = i >> 5, q = i & 31;
        uint4 v = ((const uint4*)(g_wt16 + (size_t)row * NOUT))[q];
        *(uint4*)(s_b + row * B_LD + q * 8) = v;
    }
    if (tid < 256) s_bias[tid] = bias[tid];
    else if (tid < 384) s_eg[tid - 256] = eg[tid - 256];
    else if (tid < 512) s_eb[tid - 384] = eb[tid - 384];
    __syncthreads();

    const int tiles = (N_EDGES + TILE_M - 1) / TILE_M;

    for (int t = blockIdx.x; t < tiles; t += gridDim.x) {
        const int tb = t * TILE_M;

        // ---- stage edge indices ----
        if (tid < 128) {
            const int e = tb + tid;
            s_src[tid] = (e < N_EDGES) ? ei[e] : 0;
        } else if (tid < 256) {
            const int e = tb + tid - 128;
            s_dst[tid - 128] = (e < N_EDGES) ? ei[N_EDGES + e] : 0;
        }

        wmma::fragment<wmma::accumulator, 16, 16, 16, float> acc[2][4];
#pragma unroll
        for (int r = 0; r < 2; r++)
#pragma unroll
            for (int nc = 0; nc < 4; nc++)
                wmma::fill_fragment(acc[r][nc], 0.0f);
        __syncthreads();

        // ---- 6 K-chunks of 64 ----
#pragma unroll 1
        for (int c = 0; c < 6; c++) {
            // build A chunk [128 x 64] fp16
            if (c < 4) {
                const int node = (c < 2) ? s_src[row4] : s_dst[row4];
                const int part = c & 1;
                const uint4* sp = (const uint4*)(g_xn16 + (size_t)node * FD + part * 64 + q4 * 16);
                uint4 v0 = sp[0], v1 = sp[1];
                uint4* dp = (uint4*)(s_a + row4 * A_LD + q4 * 16);
                dp[0] = v0; dp[1] = v1;
            } else {
                const int eidx = tb + row4;
                const int part = c & 1;
                union { __half2 h[8]; uint4 u[2]; } cv;
                if (eidx < N_EDGES) {
                    const float4* sp = (const float4*)(ea + (size_t)eidx * FD + part * 64 + q4 * 16);
#pragma unroll
                    for (int i = 0; i < 4; i++) {
                        float4 f = sp[i];
                        cv.h[2 * i]     = __floats2half2_rn(f.x, f.y);
                        cv.h[2 * i + 1] = __floats2half2_rn(f.z, f.w);
                    }
                } else {
                    cv.u[0] = make_uint4(0, 0, 0, 0);
                    cv.u[1] = cv.u[0];
                }
                uint4* dp = (uint4*)(s_a + row4 * A_LD + q4 * 16);
                dp[0] = cv.u[0]; dp[1] = cv.u[1];
            }
            __syncthreads();

            // MMA over this chunk
#pragma unroll
            for (int kk = 0; kk < 4; kk++) {
                wmma::fragment<wmma::matrix_a, 16, 16, 16, half, wmma::row_major> af[2];
                wmma::load_matrix_sync(af[0], s_a + (warp_row * 32)      * A_LD + kk * 16, A_LD);
                wmma::load_matrix_sync(af[1], s_a + (warp_row * 32 + 16) * A_LD + kk * 16, A_LD);
#pragma unroll
                for (int nc = 0; nc < 4; nc++) {
                    wmma::fragment<wmma::matrix_b, 16, 16, 16, half, wmma::row_major> bf;
                    wmma::load_matrix_sync(bf, s_b + (c * 64 + kk * 16) * B_LD + warp_col * 64 + nc * 16, B_LD);
                    wmma::mma_sync(acc[0][nc], af[0], bf, acc[0][nc]);
                    wmma::mma_sync(acc[1][nc], af[1], bf, acc[1][nc]);
                }
            }
            __syncthreads();
        }

        // ---- epilogue: 8 bands of 16 rows through the C slab ----
#pragma unroll 1
        for (int fr = 0; fr < 8; fr++) {
            if (warp_row == (fr >> 1)) {
#pragma unroll
                for (int nc = 0; nc < 4; nc++)
                    wmma::store_matrix_sync(slab + warp_col * 64 + nc * 16,
                                            acc[fr & 1][nc], SLAB_LD, wmma::mem_row_major);
            }
            __syncthreads();

            // warp w handles slab row w (one edge)
            {
                const int eidx = tb + fr * 16 + wid;
                const bool valid = eidx < N_EDGES;
                const float* srow = slab + wid * SLAB_LD;
                float4 d = *(const float4*)(srow + lane * 4);
                float4 g = *(const float4*)(srow + 128 + lane * 4);
                float4 e = valid ? *(const float4*)(ea + (size_t)eidx * FD + lane * 4)
                                 : make_float4(0.f, 0.f, 0.f, 0.f);
                const int j0 = lane * 4;
                float dv[4] = {d.x, d.y, d.z, d.w};
                float gv[4] = {g.x, g.y, g.z, g.w};
                float ev[4] = {e.x, e.y, e.z, e.w};
                float v[4];
                float s = 0.f, q = 0.f;
#pragma unroll
                for (int j = 0; j < 4; j++) {
                    float dlt = fmaxf(dv[j] + s_bias[j0 + j], 0.f);
                    float gat = fmaxf(gv[j] + s_bias[128 + j0 + j], 0.f);
                    float sig = __frcp_rn(1.f + __expf(-gat));
                    float val = fmaf(dlt, sig, ev[j]);
                    v[j] = val;
                    s += val;
                    q = fmaf(val, val, q);
                }
#pragma unroll
                for (int o = 16; o; o >>= 1) {
                    s += __shfl_xor_sync(0xffffffffu, s, o);
                    q += __shfl_xor_sync(0xffffffffu, q, o);
                }
                const float mu  = s * (1.f / FD);
                const float var = q * (1.f / FD) - mu * mu;
                const float rs  = rsqrtf(var + 1e-5f);
                if (valid) {
                    float4 o4;
                    o4.x = (v[0] - mu) * rs * s_eg[j0 + 0] + s_eb[j0 + 0];
                    o4.y = (v[1] - mu) * rs * s_eg[j0 + 1] + s_eb[j0 + 1];
                    o4.z = (v[2] - mu) * rs * s_eg[j0 + 2] + s_eb[j0 + 2];
                    o4.w = (v[3] - mu) * rs * s_eg[j0 + 3] + s_eb[j0 + 3];
                    *(float4*)(out + (size_t)eidx * FD + j0) = o4;
                }
            }
            __syncthreads();
        }
    }
}

// =====================================================================
// launch
// =====================================================================
extern "C" void kernel_launch(void* const* d_in, const int* in_sizes, int n_in,
                              void* d_out, int out_size) {
    const float* x  = (const float*)d_in[0];
    const int*   ei = (const int*)d_in[1];
    const float* ea = (const float*)d_in[2];
    const float* W  = (const float*)d_in[3];
    const float* b  = (const float*)d_in[4];
    const float* ng = (const float*)d_in[5];
    const float* nb = (const float*)d_in[6];
    const float* eg = (const float*)d_in[7];
    const float* eb = (const float*)d_in[8];
    float* out = (float*)d_out;

    node_prep_kernel<<<N_NODES, FD>>>(x, ng, nb);
    w_prep_kernel<<<(KDIM * NOUT) / 256, 256>>>(W);

    cudaFuncSetAttribute(edge_kernel, cudaFuncAttributeMaxDynamicSharedMemorySize, SMEM_TOTAL);
    int nsm = 148;
    cudaDeviceGetAttribute(&nsm, cudaDevAttrMultiProcessorCount, 0);
    edge_kernel<<<nsm, 512, SMEM_TOTAL>>>(ei, ea, b, eg, eb, out);
}

// round 3
// speedup vs baseline: 1.6123x; 1.6123x over previous
#include <cuda_runtime.h>
#include <cuda_fp16.h>
#include <cstdint>

// ---------------- problem constants ----------------
#define N_NODES 50000
#define N_EDGES 500000
#define FD      128
#define KDIM    384
#define NOUT    256
#define TILE_M  128
#define NTILES  ((N_EDGES + TILE_M - 1) / TILE_M)

// ---------------- smem layout ----------------
#define B_OFF       0
#define B_BYTES     (6 * 32768)              // 6 K-blocks [256 n-rows x 64 halves], swizzled
#define A_OFF       B_BYTES                  // 196608
#define A_BUF       16384                    // one chunk [128 rows x 64 halves], swizzled
#define IDX_OFF     (A_OFF + 2 * A_BUF)      // 229376
#define PAR_OFF     (IDX_OFF + 1024)         // 230400
#define SMEM_TOTAL  (PAR_OFF + 2048)         // 232448 == 227 KB max opt-in

// ---------------- device scratch ----------------
__device__ __align__(256) __half        g_xn16[(size_t)N_NODES * FD];
__device__ __align__(256) __half        g_ea16[(size_t)N_EDGES * FD];
__device__ __align__(256) unsigned char g_wt16[B_BYTES];

// ---------------- ptx helpers ----------------
__device__ __forceinline__ uint32_t smem_u32(const void* p) {
    uint32_t a;
    asm("{ .reg .u64 t; cvta.to.shared.u64 t, %1; cvt.u32.u64 %0, t; }" : "=r"(a) : "l"(p));
    return a;
}
__device__ __forceinline__ void cpa16(uint32_t s, const void* g) {
    asm volatile("cp.async.cg.shared.global [%0], [%1], 16;" :: "r"(s), "l"(g));
}
#define CP_COMMIT() asm volatile("cp.async.commit_group;" ::: "memory")
#define CP_WAIT0()  asm volatile("cp.async.wait_group 0;" ::: "memory")

__device__ __forceinline__ void ldsm4(uint32_t* r, uint32_t addr) {
    asm volatile("ldmatrix.sync.aligned.m8n8.x4.shared.b16 {%0,%1,%2,%3}, [%4];"
                 : "=r"(r[0]), "=r"(r[1]), "=r"(r[2]), "=r"(r[3]) : "r"(addr));
}
__device__ __forceinline__ void mma16816(float* c, const uint32_t* a, uint32_t b0, uint32_t b1) {
    asm volatile("mma.sync.aligned.m16n8k16.row.col.f32.f16.f16.f32 "
                 "{%0,%1,%2,%3}, {%4,%5,%6,%7}, {%8,%9}, {%0,%1,%2,%3};"
                 : "+f"(c[0]), "+f"(c[1]), "+f"(c[2]), "+f"(c[3])
                 : "r"(a[0]), "r"(a[1]), "r"(a[2]), "r"(a[3]), "r"(b0), "r"(b1));
}

// =====================================================================
// prep kernels
// =====================================================================
__global__ void node_prep(const float* __restrict__ x, const float* __restrict__ ng,
                          const float* __restrict__ nb) {
    const int wid = threadIdx.x >> 5, lane = threadIdx.x & 31;
    const int node = blockIdx.x * 8 + wid;
    if (node >= N_NODES) return;
    float4 v = *(const float4*)(x + (size_t)node * FD + lane * 4);
    float s = v.x + v.y + v.z + v.w;
    float q = v.x * v.x + v.y * v.y + v.z * v.z + v.w * v.w;
#pragma unroll
    for (int o = 16; o; o >>= 1) {
        s += __shfl_xor_sync(~0u, s, o);
        q += __shfl_xor_sync(~0u, q, o);
    }
    const float mu = s * (1.f / FD), var = q * (1.f / FD) - mu * mu;
    const float rs = rsqrtf(var + 1e-5f);
    float4 g = *(const float4*)(ng + lane * 4);
    float4 b = *(const float4*)(nb + lane * 4);
    union { __half2 h[2]; uint2 u; } o;
    o.h[0] = __floats2half2_rn((v.x - mu) * rs * g.x + b.x, (v.y - mu) * rs * g.y + b.y);
    o.h[1] = __floats2half2_rn((v.z - mu) * rs * g.z + b.z, (v.w - mu) * rs * g.w + b.w);
    *(uint2*)(g_xn16 + (size_t)node * FD + lane * 4) = o.u;
}

__global__ void ea_prep(const float* __restrict__ ea) {
    const size_t i = ((size_t)blockIdx.x * 256 + threadIdx.x) * 8;
    float4 f0 = *(const float4*)(ea + i);
    float4 f1 = *(const float4*)(ea + i + 4);
    union { __half2 h[4]; uint4 u; } o;
    o.h[0] = __floats2half2_rn(f0.x, f0.y);
    o.h[1] = __floats2half2_rn(f0.z, f0.w);
    o.h[2] = __floats2half2_rn(f1.x, f1.y);
    o.h[3] = __floats2half2_rn(f1.z, f1.w);
    *(uint4*)(g_ea16 + i) = o.u;
}

// W [K=384, N=256] f32 -> Wt blocks: 6 K-blocks of [256 n-rows x 64 halves], XOR-swizzled
__global__ void w_prep(const float* __restrict__ W) {
    const int n = blockIdx.x;       // 0..255
    const int t = threadIdx.x;      // 0..47
    const int k0 = t * 8;
    const int kb = k0 >> 6, kl = k0 & 63;
    union { __half h[8]; uint4 u; } pk;
#pragma unroll
    for (int i = 0; i < 8; i++) pk.h[i] = __float2half_rn(W[(k0 + i) * NOUT + n]);
    const uint32_t phys = kb * 32768 + n * 128 + ((((kl >> 3) ^ (n & 7))) << 4);
    *(uint4*)(g_wt16 + phys) = pk.u;
}

// =====================================================================
// fused edge kernel: raw mma pipeline, persistent CTAs
// =====================================================================
__global__ void __launch_bounds__(512, 1)
edge_kernel(const int* __restrict__ ei, const float* __restrict__ ea,
            const float* __restrict__ bias, const float* __restrict__ eg,
            const float* __restrict__ eb, float* __restrict__ out) {
    extern __shared__ char smem[];
    const uint32_t sm_u = smem_u32(smem);
    const uint32_t bB = sm_u + B_OFF;
    const uint32_t bA = sm_u + A_OFF;

    int*   s_src  = (int*)(smem + IDX_OFF);
    int*   s_dst  = s_src + 128;
    float* s_bias = (float*)(smem + PAR_OFF);
    float* s_eg   = s_bias + 256;
    float* s_eb   = s_eg + 128;
    float* slab   = (float*)(smem + A_OFF);   // 32 x 256 f32, aliases A bufs

    const int tid = threadIdx.x;
    const int wid = tid >> 5, lane = tid & 31;
    const int wr = wid >> 2;        // m-group: rows wr*32..+31
    const int wc = wid & 3;         // n-group: cols wc*64..+63
    const int row4 = tid >> 2, q4 = tid & 3;
    const int r7 = row4 & 7;

    // ---- stage resident B (byte copy of pre-swizzled Wt) + params ----
    {
        const uint4* src = (const uint4*)g_wt16;
        uint4* dst = (uint4*)(smem + B_OFF);
        for (int i = tid; i < B_BYTES / 16; i += 512) dst[i] = src[i];
    }
    if (tid < 256) s_bias[tid] = bias[tid];
    else if (tid < 384) s_eg[tid - 256] = eg[tid - 256];
    else s_eb[tid - 384] = eb[tid - 384];

    // ---- ldmatrix lane addressing (precomputed) ----
    const int li = lane & 7, grp = lane >> 3;
    uint32_t a_off[2]; int a_r7[2];
#pragma unroll
    for (int s = 0; s < 2; s++) {
        const int row = wr * 32 + s * 16 + li + (grp & 1) * 8;
        a_off[s] = row * 128;
        a_r7[s] = row & 7;
    }
    const int a_qb = grp >> 1;
    uint32_t b_off[4]; int b_r7[4];
#pragma unroll
    for (int j = 0; j < 4; j++) {
        const int rn = wc * 64 + j * 16 + li + (grp >> 1) * 8;
        b_off[j] = rn * 128;
        b_r7[j] = rn & 7;
    }
    const int b_qb = grp & 1;

    // A-build cp.async destination offsets for this thread (two 16B chunks)
    const uint32_t d_off0 = row4 * 128 + (((2 * q4) ^ r7) << 4);
    const uint32_t d_off1 = row4 * 128 + (((2 * q4 + 1) ^ r7) << 4);

    __syncthreads();

    for (int t = blockIdx.x; t < NTILES; t += gridDim.x) {
        const int tb = t * TILE_M;

        // ---- stage edge indices ----
        if (tid < 128) {
            const int e = tb + tid;
            s_src[tid] = (e < N_EDGES) ? ei[e] : 0;
        } else if (tid < 256) {
            const int e = tb + tid - 128;
            s_dst[tid - 128] = (e < N_EDGES) ? ei[N_EDGES + e] : 0;
        }
        float acc[2][8][4];
#pragma unroll
        for (int s = 0; s < 2; s++)
#pragma unroll
            for (int n = 0; n < 8; n++)
#pragma unroll
                for (int i = 0; i < 4; i++) acc[s][n][i] = 0.f;
        __syncthreads();

        const int e_row = tb + row4 < N_EDGES ? tb + row4 : N_EDGES - 1;

        // ---- prologue: chunk 0 (src, part 0) ----
        {
            const char* g = (const char*)(g_xn16 + (size_t)s_src[row4] * FD) + q4 * 32;
            cpa16(bA + d_off0, g);
            cpa16(bA + d_off1, g + 16);
            CP_COMMIT();
        }

        // ---- pipelined 6 chunks of K=64 ----
#pragma unroll 1
        for (int c = 0; c < 6; c++) {
            CP_WAIT0();
            __syncthreads();

            if (c < 5) {
                const int nc = c + 1;
                const char* g;
                if (nc < 2)      g = (const char*)(g_xn16 + (size_t)s_src[row4] * FD + (nc & 1) * 64) + q4 * 32;
                else if (nc < 4) g = (const char*)(g_xn16 + (size_t)s_dst[row4] * FD + (nc & 1) * 64) + q4 * 32;
                else             g = (const char*)(g_ea16 + (size_t)e_row * FD + (nc & 1) * 64) + q4 * 32;
                const uint32_t db = bA + (nc & 1) * A_BUF;
                cpa16(db + d_off0, g);
                cpa16(db + d_off1, g + 16);
                CP_COMMIT();
            }

            // MMA on chunk c
            const uint32_t abuf = bA + (c & 1) * A_BUF;
            const uint32_t bblk = bB + c * 32768;
#pragma unroll
            for (int ks = 0; ks < 4; ks++) {
                uint32_t A[2][4];
#pragma unroll
                for (int s = 0; s < 2; s++)
                    ldsm4(A[s], abuf + a_off[s] + ((((2 * ks + a_qb) ^ a_r7[s])) << 4));
                uint32_t Bv[4][4];
#pragma unroll
                for (int j = 0; j < 4; j++)
                    ldsm4(Bv[j], bblk + b_off[j] + ((((2 * ks + b_qb) ^ b_r7[j])) << 4));
#pragma unroll
                for (int s = 0; s < 2; s++)
#pragma unroll
                    for (int j = 0; j < 4; j++) {
                        mma16816(acc[s][2 * j],     A[s], Bv[j][0], Bv[j][1]);
                        mma16816(acc[s][2 * j + 1], A[s], Bv[j][2], Bv[j][3]);
                    }
            }
        }
        __syncthreads();   // all MMA done before slab overwrites A bufs

        // ---- epilogue: 4 bands of 32 rows ----
#pragma unroll 1
        for (int fr = 0; fr < 4; fr++) {
            if (wr == fr) {
#pragma unroll
                for (int s = 0; s < 2; s++)
#pragma unroll
                    for (int n = 0; n < 8; n++) {
                        const int r0 = s * 16 + (lane >> 2);
                        const int cc = wc * 64 + n * 8 + (lane & 3) * 2;
                        *(float2*)(slab + r0 * 256 + cc)       = make_float2(acc[s][n][0], acc[s][n][1]);
                        *(float2*)(slab + (r0 + 8) * 256 + cc) = make_float2(acc[s][n][2], acc[s][n][3]);
                    }
            }
            __syncthreads();

#pragma unroll
            for (int rr = 0; rr < 2; rr++) {
                const int r = wid + rr * 16;
                const int e = tb + fr * 32 + r;
                const bool valid = e < N_EDGES;
                const float* srow = slab + r * 256;
                float4 d  = *(const float4*)(srow + lane * 4);
                float4 gt = *(const float4*)(srow + 128 + lane * 4);
                float4 ev = valid ? *(const float4*)(ea + (size_t)e * FD + lane * 4)
                                  : make_float4(0.f, 0.f, 0.f, 0.f);
                const int j0 = lane * 4;
                float dv[4] = {d.x, d.y, d.z, d.w};
                float gv[4] = {gt.x, gt.y, gt.z, gt.w};
                float av[4] = {ev.x, ev.y, ev.z, ev.w};
                float v[4], s = 0.f, q = 0.f;
#pragma unroll
                for (int j = 0; j < 4; j++) {
                    float dlt = fmaxf(dv[j] + s_bias[j0 + j], 0.f);
                    float gat = fmaxf(gv[j] + s_bias[128 + j0 + j], 0.f);
                    float sig = __frcp_rn(1.f + __expf(-gat));
                    float val = fmaf(dlt, sig, av[j]);
                    v[j] = val;
                    s += val;
                    q = fmaf(val, val, q);
                }
#pragma unroll
                for (int o = 16; o; o >>= 1) {
                    s += __shfl_xor_sync(~0u, s, o);
                    q += __shfl_xor_sync(~0u, q, o);
                }
                const float mu = s * (1.f / FD), var = q * (1.f / FD) - mu * mu;
                const float rs = rsqrtf(var + 1e-5f);
                if (valid) {
                    float4 o4;
                    o4.x = (v[0] - mu) * rs * s_eg[j0 + 0] + s_eb[j0 + 0];
                    o4.y = (v[1] - mu) * rs * s_eg[j0 + 1] + s_eb[j0 + 1];
                    o4.z = (v[2] - mu) * rs * s_eg[j0 + 2] + s_eb[j0 + 2];
                    o4.w = (v[3] - mu) * rs * s_eg[j0 + 3] + s_eb[j0 + 3];
                    *(float4*)(out + (size_t)e * FD + j0) = o4;
                }
            }
            __syncthreads();
        }
    }
}

// =====================================================================
// launch
// =====================================================================
extern "C" void kernel_launch(void* const* d_in, const int* in_sizes, int n_in,
                              void* d_out, int out_size) {
    const float* x  = (const float*)d_in[0];
    const int*   ei = (const int*)d_in[1];
    const float* ea = (const float*)d_in[2];
    const float* W  = (const float*)d_in[3];
    const float* b  = (const float*)d_in[4];
    const float* ng = (const float*)d_in[5];
    const float* nb = (const float*)d_in[6];
    const float* eg = (const float*)d_in[7];
    const float* eb = (const float*)d_in[8];
    float* out = (float*)d_out;

    node_prep<<<(N_NODES + 7) / 8, 256>>>(x, ng, nb);
    ea_prep<<<(N_EDGES * FD) / (256 * 8), 256>>>(ea);
    w_prep<<<NOUT, KDIM / 8>>>(W);

    cudaFuncSetAttribute(edge_kernel, cudaFuncAttributeMaxDynamicSharedMemorySize, SMEM_TOTAL);
    int nsm = 148;
    cudaDeviceGetAttribute(&nsm, cudaDevAttrMultiProcessorCount, 0);
    edge_kernel<<<nsm, 512, SMEM_TOTAL>>>(ei, ea, b, eg, eb, out);
}

// round 4
// speedup vs baseline: 2.0461x; 1.2691x over previous
#include <cuda_runtime.h>
#include <cuda_fp16.h>
#include <cstdint>

// ---------------- problem constants ----------------
#define N_NODES 50000
#define N_EDGES 500000
#define FD      128
#define KDIM    384
#define NOUT    256
#define TILE_M  128
#define NTILES  ((N_EDGES + TILE_M - 1) / TILE_M)

// ---------------- smem layout ----------------
#define B_OFF       0
#define B_BYTES     (6 * 32768)              // 6 K-blocks [256 n-rows x 64 halves], swizzled
#define A_OFF       B_BYTES                  // 196608
#define A_BUF       16384                    // one chunk [128 rows x 64 halves], swizzled
#define IDX_OFF     (A_OFF + 2 * A_BUF)      // 229376 : src[128] dst[128]
#define PSUM_OFF    (IDX_OFF + 1024)         // 230400 : 128 rows x (s,q) f32 = 1KB
#define SMEM_TOTAL  (PSUM_OFF + 1024)        // 231424 <= 232448

// ---------------- device scratch ----------------
__device__ __align__(256) __half        g_xn16[(size_t)N_NODES * FD];
__device__ __align__(256) __half        g_ea16[(size_t)N_EDGES * FD];
__device__ __align__(256) unsigned char g_wt16[B_BYTES];

// ---------------- ptx helpers ----------------
__device__ __forceinline__ uint32_t smem_u32(const void* p) {
    uint32_t a;
    asm("{ .reg .u64 t; cvta.to.shared.u64 t, %1; cvt.u32.u64 %0, t; }" : "=r"(a) : "l"(p));
    return a;
}
__device__ __forceinline__ void cpa16(uint32_t s, const void* g) {
    asm volatile("cp.async.cg.shared.global [%0], [%1], 16;" :: "r"(s), "l"(g));
}
#define CP_COMMIT() asm volatile("cp.async.commit_group;" ::: "memory")
#define CP_WAIT0()  asm volatile("cp.async.wait_group 0;" ::: "memory")

__device__ __forceinline__ void ldsm4(uint32_t* r, uint32_t addr) {
    asm volatile("ldmatrix.sync.aligned.m8n8.x4.shared.b16 {%0,%1,%2,%3}, [%4];"
                 : "=r"(r[0]), "=r"(r[1]), "=r"(r[2]), "=r"(r[3]) : "r"(addr));
}
__device__ __forceinline__ void mma16816(float* c, const uint32_t* a, uint32_t b0, uint32_t b1) {
    asm volatile("mma.sync.aligned.m16n8k16.row.col.f32.f16.f16.f32 "
                 "{%0,%1,%2,%3}, {%4,%5,%6,%7}, {%8,%9}, {%0,%1,%2,%3};"
                 : "+f"(c[0]), "+f"(c[1]), "+f"(c[2]), "+f"(c[3])
                 : "r"(a[0]), "r"(a[1]), "r"(a[2]), "r"(a[3]), "r"(b0), "r"(b1));
}

// =====================================================================
// prep kernels
// =====================================================================
__global__ void node_prep(const float* __restrict__ x, const float* __restrict__ ng,
                          const float* __restrict__ nb) {
    const int wid = threadIdx.x >> 5, lane = threadIdx.x & 31;
    const int node = blockIdx.x * 8 + wid;
    if (node >= N_NODES) return;
    float4 v = *(const float4*)(x + (size_t)node * FD + lane * 4);
    float s = v.x + v.y + v.z + v.w;
    float q = v.x * v.x + v.y * v.y + v.z * v.z + v.w * v.w;
#pragma unroll
    for (int o = 16; o; o >>= 1) {
        s += __shfl_xor_sync(~0u, s, o);
        q += __shfl_xor_sync(~0u, q, o);
    }
    const float mu = s * (1.f / FD), var = q * (1.f / FD) - mu * mu;
    const float rs = rsqrtf(var + 1e-5f);
    float4 g = *(const float4*)(ng + lane * 4);
    float4 b = *(const float4*)(nb + lane * 4);
    union { __half2 h[2]; uint2 u; } o;
    o.h[0] = __floats2half2_rn((v.x - mu) * rs * g.x + b.x, (v.y - mu) * rs * g.y + b.y);
    o.h[1] = __floats2half2_rn((v.z - mu) * rs * g.z + b.z, (v.w - mu) * rs * g.w + b.w);
    *(uint2*)(g_xn16 + (size_t)node * FD + lane * 4) = o.u;
}

__global__ void ea_prep(const float* __restrict__ ea) {
    const size_t i = ((size_t)blockIdx.x * 256 + threadIdx.x) * 8;
    float4 f0 = *(const float4*)(ea + i);
    float4 f1 = *(const float4*)(ea + i + 4);
    union { __half2 h[4]; uint4 u; } o;
    o.h[0] = __floats2half2_rn(f0.x, f0.y);
    o.h[1] = __floats2half2_rn(f0.z, f0.w);
    o.h[2] = __floats2half2_rn(f1.x, f1.y);
    o.h[3] = __floats2half2_rn(f1.z, f1.w);
    *(uint4*)(g_ea16 + i) = o.u;
}

// W [K=384, N=256] f32 -> Wt blocks, COLUMN-PERMUTED so each 64-col strip is
// [delta feats f..f+31 | gate feats f..f+31] for f = strip*32.
// phys: 6 K-blocks of [256 n-rows x 64 halves], XOR-swizzled.
__global__ void w_prep(const float* __restrict__ W) {
    const int n = blockIdx.x;            // permuted col 0..255
    const int blkN = n >> 6, j = n & 63;
    const int f = blkN * 32 + (j & 31);
    const int src = (j < 32) ? f : (128 + f);   // original W column
    const int t = threadIdx.x;           // 0..47
    const int k0 = t * 8;
    const int kb = k0 >> 6, kl = k0 & 63;
    union { __half h[8]; uint4 u; } pk;
#pragma unroll
    for (int i = 0; i < 8; i++) pk.h[i] = __float2half_rn(W[(k0 + i) * NOUT + src]);
    const uint32_t phys = kb * 32768 + n * 128 + ((((kl >> 3) ^ (n & 7))) << 4);
    *(uint4*)(g_wt16 + phys) = pk.u;
}

// =====================================================================
// fused edge kernel
// =====================================================================
__global__ void __launch_bounds__(512, 1)
edge_kernel(const int* __restrict__ ei, const float* __restrict__ bias,
            const float* __restrict__ eg, const float* __restrict__ eb,
            float* __restrict__ out) {
    extern __shared__ char smem[];
    const uint32_t sm_u = smem_u32(smem);
    const uint32_t bB = sm_u + B_OFF;
    const uint32_t bA = sm_u + A_OFF;

    int*   s_src = (int*)(smem + IDX_OFF);
    int*   s_dst = s_src + 128;
    float* psum  = (float*)(smem + PSUM_OFF);   // [128][2]

    const int tid = threadIdx.x;
    const int wid = tid >> 5, lane = tid & 31;
    const int wr = wid >> 2;        // m-group: rows wr*32..+31
    const int wc = wid & 3;         // n-group: permuted cols wc*64..+63
    const int row4 = tid >> 2, q4 = tid & 3;
    const int r7 = row4 & 7;
    const int lq = lane & 3, lr = lane >> 2;

    // ---- stage resident B (byte copy of pre-swizzled, pre-permuted Wt) ----
    {
        const uint4* src = (const uint4*)g_wt16;
        uint4* dst = (uint4*)(smem + B_OFF);
        for (int i = tid; i < B_BYTES / 16; i += 512) dst[i] = src[i];
    }

    // ---- ldmatrix lane addressing ----
    const int li = lane & 7, grp = lane >> 3;
    uint32_t a_off[2]; int a_r7[2];
#pragma unroll
    for (int s = 0; s < 2; s++) {
        const int row = wr * 32 + s * 16 + li + (grp & 1) * 8;
        a_off[s] = row * 128;
        a_r7[s] = row & 7;
    }
    const int a_qb = grp >> 1;
    uint32_t b_off[4]; int b_r7[4];
#pragma unroll
    for (int j = 0; j < 4; j++) {
        const int rn = wc * 64 + j * 16 + li + (grp >> 1) * 8;
        b_off[j] = rn * 128;
        b_r7[j] = rn & 7;
    }
    const int b_qb = grp & 1;

    // A-build cp.async destinations (two 16B chunks per thread)
    const uint32_t d_off0 = row4 * 128 + (((2 * q4) ^ r7) << 4);
    const uint32_t d_off1 = row4 * 128 + (((2 * q4 + 1) ^ r7) << 4);

    // epilogue residual LDS base: warp wc reads feats wc*32..+31 -> buf (wc>>1)
    const uint32_t res_base = bA + (wc >> 1) * A_BUF;

    __syncthreads();

    for (int t = blockIdx.x; t < NTILES; t += gridDim.x) {
        const int tb = t * TILE_M;

        // ---- stage edge indices + zero psum ----
        if (tid < 128) {
            const int e = tb + tid;
            s_src[tid] = (e < N_EDGES) ? ei[e] : 0;
        } else if (tid < 256) {
            const int e = tb + tid - 128;
            s_dst[tid - 128] = (e < N_EDGES) ? ei[N_EDGES + e] : 0;
        } else if (tid < 512) {
            psum[tid - 256] = 0.f;
        }
        float acc[2][8][4];
#pragma unroll
        for (int s = 0; s < 2; s++)
#pragma unroll
            for (int n = 0; n < 8; n++)
#pragma unroll
                for (int i = 0; i < 4; i++) acc[s][n][i] = 0.f;
        __syncthreads();

        const int e_row = tb + row4 < N_EDGES ? tb + row4 : N_EDGES - 1;

        // ---- prologue: chunk 0 (src, feats 0-63) ----
        {
            const char* g = (const char*)(g_xn16 + (size_t)s_src[row4] * FD) + q4 * 32;
            cpa16(bA + d_off0, g);
            cpa16(bA + d_off1, g + 16);
            CP_COMMIT();
        }

        // ---- pipelined 6 chunks of K=64 ----
#pragma unroll 1
        for (int c = 0; c < 6; c++) {
            CP_WAIT0();
            __syncthreads();

            if (c < 5) {
                const int nc = c + 1;
                const char* g;
                if (nc < 2)      g = (const char*)(g_xn16 + (size_t)s_src[row4] * FD + (nc & 1) * 64) + q4 * 32;
                else if (nc < 4) g = (const char*)(g_xn16 + (size_t)s_dst[row4] * FD + (nc & 1) * 64) + q4 * 32;
                else             g = (const char*)(g_ea16 + (size_t)e_row * FD + (nc & 1) * 64) + q4 * 32;
                const uint32_t db = bA + (nc & 1) * A_BUF;
                cpa16(db + d_off0, g);
                cpa16(db + d_off1, g + 16);
                CP_COMMIT();
            }

            const uint32_t abuf = bA + (c & 1) * A_BUF;
            const uint32_t bblk = bB + c * 32768;
#pragma unroll
            for (int ks = 0; ks < 4; ks++) {
                uint32_t A[2][4];
#pragma unroll
                for (int s = 0; s < 2; s++)
                    ldsm4(A[s], abuf + a_off[s] + ((((2 * ks + a_qb) ^ a_r7[s])) << 4));
                uint32_t Bv[4][4];
#pragma unroll
                for (int j = 0; j < 4; j++)
                    ldsm4(Bv[j], bblk + b_off[j] + ((((2 * ks + b_qb) ^ b_r7[j])) << 4));
#pragma unroll
                for (int s = 0; s < 2; s++)
#pragma unroll
                    for (int j = 0; j < 4; j++) {
                        mma16816(acc[s][2 * j],     A[s], Bv[j][0], Bv[j][1]);
                        mma16816(acc[s][2 * j + 1], A[s], Bv[j][2], Bv[j][3]);
                    }
            }
        }
        // NOTE: chunks 4/5 (= ea16 residual, feats 0-63 / 64-127) remain in A bufs.

        // ---- epilogue part 1: warp-local gated residual + row partials ----
        {
            float srs[4], qrs[4];
#pragma unroll
            for (int ri = 0; ri < 4; ri++) { srs[ri] = 0.f; qrs[ri] = 0.f; }

#pragma unroll
            for (int n = 0; n < 4; n++) {
                const int f = wc * 32 + n * 8 + lq * 2;
                const float2 bd = __ldg((const float2*)(bias + f));
                const float2 bg = __ldg((const float2*)(bias + 128 + f));
                const uint32_t colb = (wc & 1) * 64 + n * 16 + lq * 4;   // bytes within chunk
                const uint32_t unit = colb >> 4;
#pragma unroll
                for (int s = 0; s < 2; s++)
#pragma unroll
                    for (int rh = 0; rh < 2; rh++) {
                        const int row = wr * 32 + s * 16 + lr + rh * 8;
                        const uint32_t addr = res_base + row * 128
                                            + ((unit ^ (row & 7)) << 4) + (colb & 15);
                        uint32_t ru;
                        asm volatile("ld.shared.b32 %0, [%1];" : "=r"(ru) : "r"(addr));
                        const float2 res = __half22float2(*(__half2*)&ru);
                        const int ri = s * 2 + rh;
                        float d0 = fmaxf(acc[s][n][rh * 2 + 0] + bd.x, 0.f);
                        float d1 = fmaxf(acc[s][n][rh * 2 + 1] + bd.y, 0.f);
                        float g0 = fmaxf(acc[s][n + 4][rh * 2 + 0] + bg.x, 0.f);
                        float g1 = fmaxf(acc[s][n + 4][rh * 2 + 1] + bg.y, 0.f);
                        float s0 = __frcp_rn(1.f + __expf(-g0));
                        float s1 = __frcp_rn(1.f + __expf(-g1));
                        float v0 = fmaf(d0, s0, res.x);
                        float v1 = fmaf(d1, s1, res.y);
                        acc[s][n][rh * 2 + 0] = v0;
                        acc[s][n][rh * 2 + 1] = v1;
                        srs[ri] += v0 + v1;
                        qrs[ri] = fmaf(v0, v0, fmaf(v1, v1, qrs[ri]));
                    }
            }
            // quad-reduce (32-feature partials) then atomic into psum
#pragma unroll
            for (int ri = 0; ri < 4; ri++) {
                float s_ = srs[ri], q_ = qrs[ri];
                s_ += __shfl_xor_sync(~0u, s_, 1);
                q_ += __shfl_xor_sync(~0u, q_, 1);
                s_ += __shfl_xor_sync(~0u, s_, 2);
                q_ += __shfl_xor_sync(~0u, q_, 2);
                if (lq == 0) {
                    const int row = wr * 32 + (ri >> 1) * 16 + lr + (ri & 1) * 8;
                    atomicAdd(&psum[row * 2],     s_);
                    atomicAdd(&psum[row * 2 + 1], q_);
                }
            }
        }
        __syncthreads();

        // ---- epilogue part 2: LayerNorm + store ----
#pragma unroll
        for (int s = 0; s < 2; s++)
#pragma unroll
            for (int rh = 0; rh < 2; rh++) {
                const int row = wr * 32 + s * 16 + lr + rh * 8;
                const int e = tb + row;
                const float2 p = *(const float2*)(psum + row * 2);
                const float mu = p.x * (1.f / FD);
                const float var = p.y * (1.f / FD) - mu * mu;
                const float rs = rsqrtf(var + 1e-5f);
                if (e < N_EDGES) {
#pragma unroll
                    for (int n = 0; n < 4; n++) {
                        const int f = wc * 32 + n * 8 + lq * 2;
                        const float2 gg = __ldg((const float2*)(eg + f));
                        const float2 bb = __ldg((const float2*)(eb + f));
                        float2 o;
                        o.x = (acc[s][n][rh * 2 + 0] - mu) * rs * gg.x + bb.x;
                        o.y = (acc[s][n][rh * 2 + 1] - mu) * rs * gg.y + bb.y;
                        *(float2*)(out + (size_t)e * FD + f) = o;
                    }
                }
            }
        __syncthreads();   // guard psum/idx/A-bufs before next tile
    }
}

// =====================================================================
// launch
// =====================================================================
extern "C" void kernel_launch(void* const* d_in, const int* in_sizes, int n_in,
                              void* d_out, int out_size) {
    const float* x  = (const float*)d_in[0];
    const int*   ei = (const int*)d_in[1];
    const float* ea = (const float*)d_in[2];
    const float* W  = (const float*)d_in[3];
    const float* b  = (const float*)d_in[4];
    const float* ng = (const float*)d_in[5];
    const float* nb = (const float*)d_in[6];
    const float* eg = (const float*)d_in[7];
    const float* eb = (const float*)d_in[8];
    float* out = (float*)d_out;

    node_prep<<<(N_NODES + 7) / 8, 256>>>(x, ng, nb);
    ea_prep<<<(N_EDGES * FD) / (256 * 8), 256>>>(ea);
    w_prep<<<NOUT, KDIM / 8>>>(W);

    cudaFuncSetAttribute(edge_kernel, cudaFuncAttributeMaxDynamicSharedMemorySize, SMEM_TOTAL);
    int nsm = 148;
    cudaDeviceGetAttribute(&nsm, cudaDevAttrMultiProcessorCount, 0);
    edge_kernel<<<nsm, 512, SMEM_TOTAL>>>(ei, b, eg, eb, out);
}

// round 5
// speedup vs baseline: 2.0611x; 1.0073x over previous
#include <cuda_runtime.h>
#include <cuda_fp16.h>
#include <cstdint>

// ---------------- problem constants ----------------
#define N_NODES 50000
#define N_EDGES 500000
#define FD      128
#define KDIM    384
#define NOUT    256
#define TILE_M  128
#define NTILES  ((N_EDGES + TILE_M - 1) / TILE_M)
#define EA_BLOCKS ((N_EDGES * FD) / 2048)      // 31250
#define NODE_BLOCKS ((N_NODES + 7) / 8)        // 6250

// ---------------- smem layout ----------------
#define B_OFF       0
#define B_BYTES     (6 * 32768)              // 6 K-blocks [256 n-rows x 64 halves], swizzled
#define A_OFF       B_BYTES                  // 196608
#define A_BUF       16384                    // one chunk [128 rows x 64 halves], swizzled
#define IDX_OFF     (A_OFF + 2 * A_BUF)      // 229376 : src[128] dst[128]
#define PSUM_OFF    (IDX_OFF + 1024)         // 230400 : 128 rows x (s,q) f32
#define SMEM_TOTAL  (PSUM_OFF + 1024)        // 231424 <= 232448

// ---------------- device scratch ----------------
__device__ __align__(256) __half        g_xn16[(size_t)N_NODES * FD];
__device__ __align__(256) __half        g_ea16[(size_t)N_EDGES * FD];
__device__ __align__(256) unsigned char g_wt16[B_BYTES];

// ---------------- ptx helpers ----------------
__device__ __forceinline__ uint32_t smem_u32(const void* p) {
    uint32_t a;
    asm("{ .reg .u64 t; cvta.to.shared.u64 t, %1; cvt.u32.u64 %0, t; }" : "=r"(a) : "l"(p));
    return a;
}
__device__ __forceinline__ void cpa16(uint32_t s, const void* g) {
    asm volatile("cp.async.cg.shared.global [%0], [%1], 16;" :: "r"(s), "l"(g));
}
#define CP_COMMIT() asm volatile("cp.async.commit_group;" ::: "memory")
#define CP_WAIT0()  asm volatile("cp.async.wait_group 0;" ::: "memory")

__device__ __forceinline__ void ldsm4(uint32_t* r, uint32_t addr) {
    asm volatile("ldmatrix.sync.aligned.m8n8.x4.shared.b16 {%0,%1,%2,%3}, [%4];"
                 : "=r"(r[0]), "=r"(r[1]), "=r"(r[2]), "=r"(r[3]) : "r"(addr));
}
__device__ __forceinline__ void mma16816(float* c, const uint32_t* a, uint32_t b0, uint32_t b1) {
    asm volatile("mma.sync.aligned.m16n8k16.row.col.f32.f16.f16.f32 "
                 "{%0,%1,%2,%3}, {%4,%5,%6,%7}, {%8,%9}, {%0,%1,%2,%3};"
                 : "+f"(c[0]), "+f"(c[1]), "+f"(c[2]), "+f"(c[3])
                 : "r"(a[0]), "r"(a[1]), "r"(a[2]), "r"(a[3]), "r"(b0), "r"(b1));
}

// =====================================================================
// merged prep: ea f32->f16 stream + per-node LayerNorm
// =====================================================================
__global__ void prep_kernel(const float* __restrict__ x, const float* __restrict__ gma,
                            const float* __restrict__ bta, const float* __restrict__ ea) {
    if (blockIdx.x < EA_BLOCKS) {
        const size_t i = ((size_t)blockIdx.x * 256 + threadIdx.x) * 8;
        float4 f0 = *(const float4*)(ea + i);
        float4 f1 = *(const float4*)(ea + i + 4);
        union { __half2 h[4]; uint4 u; } o;
        o.h[0] = __floats2half2_rn(f0.x, f0.y);
        o.h[1] = __floats2half2_rn(f0.z, f0.w);
        o.h[2] = __floats2half2_rn(f1.x, f1.y);
        o.h[3] = __floats2half2_rn(f1.z, f1.w);
        *(uint4*)(g_ea16 + i) = o.u;
    } else {
        const int wid = threadIdx.x >> 5, lane = threadIdx.x & 31;
        const int node = (blockIdx.x - EA_BLOCKS) * 8 + wid;
        if (node >= N_NODES) return;
        float4 v = *(const float4*)(x + (size_t)node * FD + lane * 4);
        float s = v.x + v.y + v.z + v.w;
        float q = v.x * v.x + v.y * v.y + v.z * v.z + v.w * v.w;
#pragma unroll
        for (int o = 16; o; o >>= 1) {
            s += __shfl_xor_sync(~0u, s, o);
            q += __shfl_xor_sync(~0u, q, o);
        }
        const float mu = s * (1.f / FD), var = q * (1.f / FD) - mu * mu;
        const float rs = rsqrtf(var + 1e-5f);
        float4 g = *(const float4*)(gma + lane * 4);
        float4 b = *(const float4*)(bta + lane * 4);
        union { __half2 h[2]; uint2 u; } o;
        o.h[0] = __floats2half2_rn((v.x - mu) * rs * g.x + b.x, (v.y - mu) * rs * g.y + b.y);
        o.h[1] = __floats2half2_rn((v.z - mu) * rs * g.z + b.z, (v.w - mu) * rs * g.w + b.w);
        *(uint2*)(g_xn16 + (size_t)node * FD + lane * 4) = o.u;
    }
}

// W [K=384, N=256] f32 -> Wt blocks, column-permuted: strip wc holds
// [delta f..f+31 | gate f..f+31], f = strip*32. XOR-swizzled.
__global__ void w_prep(const float* __restrict__ W) {
    const int n = blockIdx.x;
    const int blkN = n >> 6, j = n & 63;
    const int f = blkN * 32 + (j & 31);
    const int src = (j < 32) ? f : (128 + f);
    const int t = threadIdx.x;
    const int k0 = t * 8;
    const int kb = k0 >> 6, kl = k0 & 63;
    union { __half h[8]; uint4 u; } pk;
#pragma unroll
    for (int i = 0; i < 8; i++) pk.h[i] = __float2half_rn(W[(k0 + i) * NOUT + src]);
    const uint32_t phys = kb * 32768 + n * 128 + ((((kl >> 3) ^ (n & 7))) << 4);
    *(uint4*)(g_wt16 + phys) = pk.u;
}

// =====================================================================
// fused edge kernel — cross-tile pipelined
// =====================================================================
__global__ void __launch_bounds__(512, 1)
edge_kernel(const int* __restrict__ ei, const float* __restrict__ bias,
            const float* __restrict__ eg, const float* __restrict__ eb,
            float* __restrict__ out) {
    extern __shared__ char smem[];
    const uint32_t sm_u = smem_u32(smem);
    const uint32_t bB = sm_u + B_OFF;
    const uint32_t bA = sm_u + A_OFF;

    int*   s_src = (int*)(smem + IDX_OFF);
    int*   s_dst = s_src + 128;
    float* psum  = (float*)(smem + PSUM_OFF);

    const int tid = threadIdx.x;
    const int wid = tid >> 5, lane = tid & 31;
    const int wr = wid >> 2;
    const int wc = wid & 3;
    const int row4 = tid >> 2, q4 = tid & 3;
    const int r7 = row4 & 7;
    const int lq = lane & 3, lr = lane >> 2;

    // ---- stage resident B ----
    {
        const uint4* src = (const uint4*)g_wt16;
        uint4* dst = (uint4*)(smem + B_OFF);
        for (int i = tid; i < B_BYTES / 16; i += 512) dst[i] = src[i];
    }

    // ---- ldmatrix lane addressing ----
    const int li = lane & 7, grp = lane >> 3;
    uint32_t a_off[2]; int a_r7[2];
#pragma unroll
    for (int s = 0; s < 2; s++) {
        const int row = wr * 32 + s * 16 + li + (grp & 1) * 8;
        a_off[s] = row * 128;
        a_r7[s] = row & 7;
    }
    const int a_qb = grp >> 1;
    uint32_t b_off[4]; int b_r7[4];
#pragma unroll
    for (int j = 0; j < 4; j++) {
        const int rn = wc * 64 + j * 16 + li + (grp >> 1) * 8;
        b_off[j] = rn * 128;
        b_r7[j] = rn & 7;
    }
    const int b_qb = grp & 1;

    const uint32_t d_off0 = row4 * 128 + (((2 * q4) ^ r7) << 4);
    const uint32_t d_off1 = row4 * 128 + (((2 * q4 + 1) ^ r7) << 4);

    // ---- prologue: stage idx for first tile, zero psum, issue chunk 0 ----
    const int t0 = blockIdx.x;
    {
        const int tb0 = t0 * TILE_M;
        if (tid < 128) {
            const int e = tb0 + tid;
            s_src[tid] = (e < N_EDGES) ? ei[e] : 0;
        } else if (tid < 256) {
            const int e = tb0 + tid - 128;
            s_dst[tid - 128] = (e < N_EDGES) ? ei[N_EDGES + e] : 0;
        } else {
            psum[tid - 256] = 0.f;
        }
    }
    __syncthreads();
    {
        const char* g = (const char*)(g_xn16 + (size_t)s_src[row4] * FD) + q4 * 32;
        cpa16(bA + d_off0, g);
        cpa16(bA + d_off1, g + 16);
        CP_COMMIT();
    }

    for (int t = t0; t < NTILES; t += gridDim.x) {
        const int tb = t * TILE_M;
        const int er = min(tb + row4, N_EDGES - 1);

        float acc[2][8][4];
#pragma unroll
        for (int s = 0; s < 2; s++)
#pragma unroll
            for (int n = 0; n < 8; n++)
#pragma unroll
                for (int i = 0; i < 4; i++) acc[s][n][i] = 0.f;

        // ---- 6 chunks of K=64, gathers issued one chunk ahead ----
#pragma unroll 1
        for (int c = 0; c < 6; c++) {
            CP_WAIT0();
            __syncthreads();

            if (c == 0) {
                if (tid >= 256) psum[tid - 256] = 0.f;
            } else if (c == 3) {
                // stage NEXT tile's indices (current tile's last idx use was c==2)
                const int tn = t + gridDim.x;
                const int tbn = tn * TILE_M;
                if (tid < 128) {
                    const int e = tbn + tid;
                    s_src[tid] = (tn < NTILES && e < N_EDGES) ? ei[e] : 0;
                } else if (tid < 256) {
                    const int e = tbn + tid - 128;
                    s_dst[tid - 128] = (tn < NTILES && e < N_EDGES) ? ei[N_EDGES + e] : 0;
                }
            }

            // issue gather for chunk c+1 (or next tile's chunk 0)
            {
                const char* g = nullptr;
                uint32_t db = 0;
                if (c == 0)      { g = (const char*)(g_xn16 + (size_t)s_src[row4] * FD + 64); db = bA + A_BUF; }
                else if (c == 1) { g = (const char*)(g_xn16 + (size_t)s_dst[row4] * FD);      db = bA; }
                else if (c == 2) { g = (const char*)(g_xn16 + (size_t)s_dst[row4] * FD + 64); db = bA + A_BUF; }
                else if (c == 3) { g = (const char*)(g_ea16 + (size_t)er * FD);               db = bA; }
                else if (c == 4) { g = (const char*)(g_ea16 + (size_t)er * FD + 64);          db = bA + A_BUF; }
                else if (t + (int)gridDim.x < NTILES) {
                    g = (const char*)(g_xn16 + (size_t)s_src[row4] * FD);                     db = bA;
                }
                if (g) {
                    cpa16(db + d_off0, g + q4 * 32);
                    cpa16(db + d_off1, g + q4 * 32 + 16);
                }
                CP_COMMIT();
            }

            // MMA on chunk c
            const uint32_t abuf = bA + (c & 1) * A_BUF;
            const uint32_t bblk = bB + c * 32768;
#pragma unroll
            for (int ks = 0; ks < 4; ks++) {
                uint32_t A[2][4];
#pragma unroll
                for (int s = 0; s < 2; s++)
                    ldsm4(A[s], abuf + a_off[s] + ((((2 * ks + a_qb) ^ a_r7[s])) << 4));
                uint32_t Bv[4][4];
#pragma unroll
                for (int j = 0; j < 4; j++)
                    ldsm4(Bv[j], bblk + b_off[j] + ((((2 * ks + b_qb) ^ b_r7[j])) << 4));
#pragma unroll
                for (int s = 0; s < 2; s++)
#pragma unroll
                    for (int j = 0; j < 4; j++) {
                        mma16816(acc[s][2 * j],     A[s], Bv[j][0], Bv[j][1]);
                        mma16816(acc[s][2 * j + 1], A[s], Bv[j][2], Bv[j][3]);
                    }
            }
        }
        // next tile's chunk-0 gather is now in flight, overlapping the epilogue.

        // ---- epilogue part 1: gated residual (residual via L2 LDG) ----
        {
            int ec4[4];
#pragma unroll
            for (int ri = 0; ri < 4; ri++)
                ec4[ri] = min(tb + wr * 32 + (ri >> 1) * 16 + lr + (ri & 1) * 8, N_EDGES - 1);

            float srs[4], qrs[4];
#pragma unroll
            for (int ri = 0; ri < 4; ri++) { srs[ri] = 0.f; qrs[ri] = 0.f; }

#pragma unroll
            for (int n = 0; n < 4; n++) {
                const int f = wc * 32 + n * 8 + lq * 2;
                const float2 bd = __ldg((const float2*)(bias + f));
                const float2 bg = __ldg((const float2*)(bias + 128 + f));
#pragma unroll
                for (int s = 0; s < 2; s++)
#pragma unroll
                    for (int rh = 0; rh < 2; rh++) {
                        const int ri = s * 2 + rh;
                        const __half2 rh2 = __ldg((const __half2*)(g_ea16 + (size_t)ec4[ri] * FD + f));
                        const float2 res = __half22float2(rh2);
                        float d0 = fmaxf(acc[s][n][rh * 2 + 0] + bd.x, 0.f);
                        float d1 = fmaxf(acc[s][n][rh * 2 + 1] + bd.y, 0.f);
                        float g0 = fmaxf(acc[s][n + 4][rh * 2 + 0] + bg.x, 0.f);
                        float g1 = fmaxf(acc[s][n + 4][rh * 2 + 1] + bg.y, 0.f);
                        float s0 = __frcp_rn(1.f + __expf(-g0));
                        float s1 = __frcp_rn(1.f + __expf(-g1));
                        float v0 = fmaf(d0, s0, res.x);
                        float v1 = fmaf(d1, s1, res.y);
                        acc[s][n][rh * 2 + 0] = v0;
                        acc[s][n][rh * 2 + 1] = v1;
                        srs[ri] += v0 + v1;
                        qrs[ri] = fmaf(v0, v0, fmaf(v1, v1, qrs[ri]));
                    }
            }
#pragma unroll
            for (int ri = 0; ri < 4; ri++) {
                float s_ = srs[ri], q_ = qrs[ri];
                s_ += __shfl_xor_sync(~0u, s_, 1);
                q_ += __shfl_xor_sync(~0u, q_, 1);
                s_ += __shfl_xor_sync(~0u, s_, 2);
                q_ += __shfl_xor_sync(~0u, q_, 2);
                if (lq == 0) {
                    const int row = wr * 32 + (ri >> 1) * 16 + lr + (ri & 1) * 8;
                    atomicAdd(&psum[row * 2],     s_);
                    atomicAdd(&psum[row * 2 + 1], q_);
                }
            }
        }
        __syncthreads();

        // ---- epilogue part 2: LayerNorm + store ----
        {
            float2 gg[4], bb[4];
#pragma unroll
            for (int n = 0; n < 4; n++) {
                const int f = wc * 32 + n * 8 + lq * 2;
                gg[n] = __ldg((const float2*)(eg + f));
                bb[n] = __ldg((const float2*)(eb + f));
            }
#pragma unroll
            for (int s = 0; s < 2; s++)
#pragma unroll
                for (int rh = 0; rh < 2; rh++) {
                    const int row = wr * 32 + s * 16 + lr + rh * 8;
                    const int e = tb + row;
                    const float2 p = *(const float2*)(psum + row * 2);
                    const float mu = p.x * (1.f / FD);
                    const float var = p.y * (1.f / FD) - mu * mu;
                    const float rs = rsqrtf(var + 1e-5f);
                    if (e < N_EDGES) {
#pragma unroll
                        for (int n = 0; n < 4; n++) {
                            const int f = wc * 32 + n * 8 + lq * 2;
                            float2 o;
                            o.x = (acc[s][n][rh * 2 + 0] - mu) * rs * gg[n].x + bb[n].x;
                            o.y = (acc[s][n][rh * 2 + 1] - mu) * rs * gg[n].y + bb[n].y;
                            *(float2*)(out + (size_t)e * FD + f) = o;
                        }
                    }
                }
        }
        // no tile-end barrier needed: c==0's syncthreads separates psum reads
        // from the next tile's psum zeroing and atomics.
    }
}

// =====================================================================
// launch
// =====================================================================
extern "C" void kernel_launch(void* const* d_in, const int* in_sizes, int n_in,
                              void* d_out, int out_size) {
    const float* x  = (const float*)d_in[0];
    const int*   ei = (const int*)d_in[1];
    const float* ea = (const float*)d_in[2];
    const float* W  = (const float*)d_in[3];
    const float* b  = (const float*)d_in[4];
    const float* ng = (const float*)d_in[5];
    const float* nb = (const float*)d_in[6];
    const float* eg = (const float*)d_in[7];
    const float* eb = (const float*)d_in[8];
    float* out = (float*)d_out;

    prep_kernel<<<EA_BLOCKS + NODE_BLOCKS, 256>>>(x, ng, nb, ea);
    w_prep<<<NOUT, KDIM / 8>>>(W);

    cudaFuncSetAttribute(edge_kernel, cudaFuncAttributeMaxDynamicSharedMemorySize, SMEM_TOTAL);
    int nsm = 148;
    cudaDeviceGetAttribute(&nsm, cudaDevAttrMultiProcessorCount, 0);
    edge_kernel<<<nsm, 512, SMEM_TOTAL>>>(ei, b, eg, eb, out);
}

// round 6
// speedup vs baseline: 2.2409x; 1.0872x over previous
#include <cuda_runtime.h>
#include <cuda_fp16.h>
#include <cstdint>

// ---------------- problem constants ----------------
#define N_NODES 50000
#define N_EDGES 500000
#define FD      128
#define KDIM    384
#define NOUT    256
#define TILE_G  64                            // edges per warpgroup tile
#define NT_G    ((N_EDGES + TILE_G - 1) / TILE_G)   // 7813
#define EA_BLOCKS ((N_EDGES * FD) / 2048)     // 31250
#define NODE_BLOCKS ((N_NODES + 7) / 8)       // 6250

// ---------------- smem layout ----------------
#define B_OFF       0
#define B_BYTES     (6 * 32768)               // 6 K-blocks [256 n-rows x 64 halves], swizzled
#define A_OFF       B_BYTES                   // 196608
#define A_BUF_G     8192                      // one chunk [64 rows x 64 halves], swizzled
#define A_G_STRIDE  (2 * A_BUF_G)             // double buffer per group
#define IDX_OFF     (A_OFF + 2 * A_G_STRIDE)  // 229376 : per group src[64]+dst[64]
#define PSUM_OFF    (IDX_OFF + 1024)          // 230400 : per group 64 x (s,q) f32
#define SMEM_TOTAL  (PSUM_OFF + 1024)         // 231424 <= 232448

// ---------------- device scratch ----------------
__device__ __align__(256) __half        g_xn16[(size_t)N_NODES * FD];
__device__ __align__(256) __half        g_ea16[(size_t)N_EDGES * FD];
__device__ __align__(256) unsigned char g_wt16[B_BYTES];

// ---------------- ptx helpers ----------------
__device__ __forceinline__ uint32_t smem_u32(const void* p) {
    uint32_t a;
    asm("{ .reg .u64 t; cvta.to.shared.u64 t, %1; cvt.u32.u64 %0, t; }" : "=r"(a) : "l"(p));
    return a;
}
__device__ __forceinline__ void cpa16(uint32_t s, const void* g) {
    asm volatile("cp.async.cg.shared.global [%0], [%1], 16;" :: "r"(s), "l"(g));
}
#define CP_COMMIT() asm volatile("cp.async.commit_group;" ::: "memory")
#define CP_WAIT0()  asm volatile("cp.async.wait_group 0;" ::: "memory")
#define GBAR(g)     asm volatile("bar.sync %0, 256;" :: "r"((g) + 1) : "memory")

__device__ __forceinline__ void ldsm4(uint32_t* r, uint32_t addr) {
    asm volatile("ldmatrix.sync.aligned.m8n8.x4.shared.b16 {%0,%1,%2,%3}, [%4];"
                 : "=r"(r[0]), "=r"(r[1]), "=r"(r[2]), "=r"(r[3]) : "r"(addr));
}
__device__ __forceinline__ void mma16816(float* c, const uint32_t* a, uint32_t b0, uint32_t b1) {
    asm volatile("mma.sync.aligned.m16n8k16.row.col.f32.f16.f16.f32 "
                 "{%0,%1,%2,%3}, {%4,%5,%6,%7}, {%8,%9}, {%0,%1,%2,%3};"
                 : "+f"(c[0]), "+f"(c[1]), "+f"(c[2]), "+f"(c[3])
                 : "r"(a[0]), "r"(a[1]), "r"(a[2]), "r"(a[3]), "r"(b0), "r"(b1));
}

// =====================================================================
// merged prep: ea f32->f16 stream + per-node LayerNorm
// =====================================================================
__global__ void prep_kernel(const float* __restrict__ x, const float* __restrict__ gma,
                            const float* __restrict__ bta, const float* __restrict__ ea) {
    if (blockIdx.x < EA_BLOCKS) {
        const size_t i = ((size_t)blockIdx.x * 256 + threadIdx.x) * 8;
        float4 f0 = *(const float4*)(ea + i);
        float4 f1 = *(const float4*)(ea + i + 4);
        union { __half2 h[4]; uint4 u; } o;
        o.h[0] = __floats2half2_rn(f0.x, f0.y);
        o.h[1] = __floats2half2_rn(f0.z, f0.w);
        o.h[2] = __floats2half2_rn(f1.x, f1.y);
        o.h[3] = __floats2half2_rn(f1.z, f1.w);
        *(uint4*)(g_ea16 + i) = o.u;
    } else {
        const int wid = threadIdx.x >> 5, lane = threadIdx.x & 31;
        const int node = (blockIdx.x - EA_BLOCKS) * 8 + wid;
        if (node >= N_NODES) return;
        float4 v = *(const float4*)(x + (size_t)node * FD + lane * 4);
        float s = v.x + v.y + v.z + v.w;
        float q = v.x * v.x + v.y * v.y + v.z * v.z + v.w * v.w;
#pragma unroll
        for (int o = 16; o; o >>= 1) {
            s += __shfl_xor_sync(~0u, s, o);
            q += __shfl_xor_sync(~0u, q, o);
        }
        const float mu = s * (1.f / FD), var = q * (1.f / FD) - mu * mu;
        const float rs = rsqrtf(var + 1e-5f);
        float4 g = *(const float4*)(gma + lane * 4);
        float4 b = *(const float4*)(bta + lane * 4);
        union { __half2 h[2]; uint2 u; } o;
        o.h[0] = __floats2half2_rn((v.x - mu) * rs * g.x + b.x, (v.y - mu) * rs * g.y + b.y);
        o.h[1] = __floats2half2_rn((v.z - mu) * rs * g.z + b.z, (v.w - mu) * rs * g.w + b.w);
        *(uint2*)(g_xn16 + (size_t)node * FD + lane * 4) = o.u;
    }
}

// W [K=384, N=256] f32 -> Wt blocks, column-permuted: strip wc holds
// [delta f..f+31 | gate f..f+31], f = strip*32. XOR-swizzled.
__global__ void w_prep(const float* __restrict__ W) {
    const int n = blockIdx.x;
    const int blkN = n >> 6, j = n & 63;
    const int f = blkN * 32 + (j & 31);
    const int src = (j < 32) ? f : (128 + f);
    const int t = threadIdx.x;
    const int k0 = t * 8;
    const int kb = k0 >> 6, kl = k0 & 63;
    union { __half h[8]; uint4 u; } pk;
#pragma unroll
    for (int i = 0; i < 8; i++) pk.h[i] = __float2half_rn(W[(k0 + i) * NOUT + src]);
    const uint32_t phys = kb * 32768 + n * 128 + ((((kl >> 3) ^ (n & 7))) << 4);
    *(uint4*)(g_wt16 + phys) = pk.u;
}

// =====================================================================
// fused edge kernel — two independent 8-warp groups per CTA
// =====================================================================
__global__ void __launch_bounds__(512, 1)
edge_kernel(const int* __restrict__ ei, const float* __restrict__ bias,
            const float* __restrict__ eg, const float* __restrict__ eb,
            float* __restrict__ out) {
    extern __shared__ char smem[];
    const uint32_t sm_u = smem_u32(smem);
    const uint32_t bB = sm_u + B_OFF;

    const int tid  = threadIdx.x;
    const int g    = tid >> 8;            // warpgroup 0 / 1
    const int ltid = tid & 255;
    const int wid_g = ltid >> 5, lane = ltid & 31;
    const int wr = wid_g >> 2;            // 0..1 : rows wr*32..+31 of 64
    const int wc = wid_g & 3;             // 0..3 : permuted cols wc*64..+63
    const int row4 = ltid >> 2, q4 = ltid & 3;   // A build: 64 rows x 4 thr
    const int r7 = row4 & 7;
    const int lq = lane & 3, lr = lane >> 2;

    const uint32_t bA = sm_u + A_OFF + g * A_G_STRIDE;
    int*   s_src = (int*)(smem + IDX_OFF) + g * 128;
    int*   s_dst = s_src + 64;
    float* psum  = (float*)(smem + PSUM_OFF) + g * 128;

    // ---- stage resident B (all 512 threads) ----
    {
        const uint4* src = (const uint4*)g_wt16;
        uint4* dst = (uint4*)(smem + B_OFF);
        for (int i = tid; i < B_BYTES / 16; i += 512) dst[i] = src[i];
    }

    // ---- ldmatrix lane addressing ----
    const int li = lane & 7, lgrp = lane >> 3;
    uint32_t a_off[2]; int a_r7[2];
#pragma unroll
    for (int s = 0; s < 2; s++) {
        const int row = wr * 32 + s * 16 + li + (lgrp & 1) * 8;
        a_off[s] = row * 128;
        a_r7[s] = row & 7;
    }
    const int a_qb = lgrp >> 1;
    uint32_t b_off[4]; int b_r7[4];
#pragma unroll
    for (int j = 0; j < 4; j++) {
        const int rn = wc * 64 + j * 16 + li + (lgrp >> 1) * 8;
        b_off[j] = rn * 128;
        b_r7[j] = rn & 7;
    }
    const int b_qb = lgrp & 1;

    const uint32_t d_off0 = row4 * 128 + (((2 * q4) ^ r7) << 4);
    const uint32_t d_off1 = row4 * 128 + (((2 * q4 + 1) ^ r7) << 4);

    __syncthreads();   // B visible to both groups; last CTA-wide barrier

    // ---- group prologue: first tile idx + psum, chunk-0 gather ----
    const int t0 = blockIdx.x * 2 + g;
    const int tstride = gridDim.x * 2;
    {
        const int tb0 = t0 * TILE_G;
        if (ltid < 64) {
            const int e = tb0 + ltid;
            s_src[ltid] = (e < N_EDGES) ? ei[e] : 0;
        } else if (ltid < 128) {
            const int e = tb0 + ltid - 64;
            s_dst[ltid - 64] = (e < N_EDGES) ? ei[N_EDGES + e] : 0;
        } else {
            psum[ltid - 128] = 0.f;
        }
    }
    GBAR(g);
    {
        const char* gp = (const char*)(g_xn16 + (size_t)s_src[row4] * FD) + q4 * 32;
        cpa16(bA + d_off0, gp);
        cpa16(bA + d_off1, gp + 16);
        CP_COMMIT();
    }

    for (int t = t0; t < NT_G; t += tstride) {
        const int tb = t * TILE_G;
        const int er = min(tb + row4, N_EDGES - 1);

        float acc[2][8][4];
#pragma unroll
        for (int s = 0; s < 2; s++)
#pragma unroll
            for (int n = 0; n < 8; n++)
#pragma unroll
                for (int i = 0; i < 4; i++) acc[s][n][i] = 0.f;

        // ---- 6 chunks of K=64, gathers one chunk ahead ----
#pragma unroll 1
        for (int c = 0; c < 6; c++) {
            CP_WAIT0();
            GBAR(g);

            if (c == 0) {
                if (ltid >= 128) psum[ltid - 128] = 0.f;
            } else if (c == 3) {
                const int tn = t + tstride;
                const int tbn = tn * TILE_G;
                if (ltid < 64) {
                    const int e = tbn + ltid;
                    s_src[ltid] = (tn < NT_G && e < N_EDGES) ? ei[e] : 0;
                } else if (ltid < 128) {
                    const int e = tbn + ltid - 64;
                    s_dst[ltid - 64] = (tn < NT_G && e < N_EDGES) ? ei[N_EDGES + e] : 0;
                }
            }

            // issue gather for chunk c+1 (or next tile's chunk 0)
            {
                const char* gp = nullptr;
                uint32_t db = 0;
                if (c == 0)      { gp = (const char*)(g_xn16 + (size_t)s_src[row4] * FD + 64); db = bA + A_BUF_G; }
                else if (c == 1) { gp = (const char*)(g_xn16 + (size_t)s_dst[row4] * FD);      db = bA; }
                else if (c == 2) { gp = (const char*)(g_xn16 + (size_t)s_dst[row4] * FD + 64); db = bA + A_BUF_G; }
                else if (c == 3) { gp = (const char*)(g_ea16 + (size_t)er * FD);               db = bA; }
                else if (c == 4) { gp = (const char*)(g_ea16 + (size_t)er * FD + 64);          db = bA + A_BUF_G; }
                else if (t + tstride < NT_G) {
                    gp = (const char*)(g_xn16 + (size_t)s_src[row4] * FD);                     db = bA;
                }
                if (gp) {
                    cpa16(db + d_off0, gp + q4 * 32);
                    cpa16(db + d_off1, gp + q4 * 32 + 16);
                }
                CP_COMMIT();
            }

            // MMA on chunk c
            const uint32_t abuf = bA + (c & 1) * A_BUF_G;
            const uint32_t bblk = bB + c * 32768;
#pragma unroll
            for (int ks = 0; ks < 4; ks++) {
                uint32_t A[2][4];
#pragma unroll
                for (int s = 0; s < 2; s++)
                    ldsm4(A[s], abuf + a_off[s] + ((((2 * ks + a_qb) ^ a_r7[s])) << 4));
                uint32_t Bv[4][4];
#pragma unroll
                for (int j = 0; j < 4; j++)
                    ldsm4(Bv[j], bblk + b_off[j] + ((((2 * ks + b_qb) ^ b_r7[j])) << 4));
#pragma unroll
                for (int s = 0; s < 2; s++)
#pragma unroll
                    for (int j = 0; j < 4; j++) {
                        mma16816(acc[s][2 * j],     A[s], Bv[j][0], Bv[j][1]);
                        mma16816(acc[s][2 * j + 1], A[s], Bv[j][2], Bv[j][3]);
                    }
            }
        }

        // ---- epilogue part 1: gated residual + row partials ----
        {
            int ec4[4];
#pragma unroll
            for (int ri = 0; ri < 4; ri++)
                ec4[ri] = min(tb + wr * 32 + (ri >> 1) * 16 + lr + (ri & 1) * 8, N_EDGES - 1);

            float srs[4], qrs[4];
#pragma unroll
            for (int ri = 0; ri < 4; ri++) { srs[ri] = 0.f; qrs[ri] = 0.f; }

#pragma unroll
            for (int n = 0; n < 4; n++) {
                const int f = wc * 32 + n * 8 + lq * 2;
                const float2 bd = __ldg((const float2*)(bias + f));
                const float2 bg = __ldg((const float2*)(bias + 128 + f));
#pragma unroll
                for (int s = 0; s < 2; s++)
#pragma unroll
                    for (int rh = 0; rh < 2; rh++) {
                        const int ri = s * 2 + rh;
                        const __half2 rh2 = __ldg((const __half2*)(g_ea16 + (size_t)ec4[ri] * FD + f));
                        const float2 res = __half22float2(rh2);
                        float d0 = fmaxf(acc[s][n][rh * 2 + 0] + bd.x, 0.f);
                        float d1 = fmaxf(acc[s][n][rh * 2 + 1] + bd.y, 0.f);
                        float g0 = fmaxf(acc[s][n + 4][rh * 2 + 0] + bg.x, 0.f);
                        float g1 = fmaxf(acc[s][n + 4][rh * 2 + 1] + bg.y, 0.f);
                        float s0 = __frcp_rn(1.f + __expf(-g0));
                        float s1 = __frcp_rn(1.f + __expf(-g1));
                        float v0 = fmaf(d0, s0, res.x);
                        float v1 = fmaf(d1, s1, res.y);
                        acc[s][n][rh * 2 + 0] = v0;
                        acc[s][n][rh * 2 + 1] = v1;
                        srs[ri] += v0 + v1;
                        qrs[ri] = fmaf(v0, v0, fmaf(v1, v1, qrs[ri]));
                    }
            }
#pragma unroll
            for (int ri = 0; ri < 4; ri++) {
                float s_ = srs[ri], q_ = qrs[ri];
                s_ += __shfl_xor_sync(~0u, s_, 1);
                q_ += __shfl_xor_sync(~0u, q_, 1);
                s_ += __shfl_xor_sync(~0u, s_, 2);
                q_ += __shfl_xor_sync(~0u, q_, 2);
                if (lq == 0) {
                    const int row = wr * 32 + (ri >> 1) * 16 + lr + (ri & 1) * 8;
                    atomicAdd(&psum[row * 2],     s_);
                    atomicAdd(&psum[row * 2 + 1], q_);
                }
            }
        }
        GBAR(g);

        // ---- epilogue part 2: LayerNorm + store ----
        {
            float2 gg[4], bb[4];
#pragma unroll
            for (int n = 0; n < 4; n++) {
                const int f = wc * 32 + n * 8 + lq * 2;
                gg[n] = __ldg((const float2*)(eg + f));
                bb[n] = __ldg((const float2*)(eb + f));
            }
#pragma unroll
            for (int s = 0; s < 2; s++)
#pragma unroll
                for (int rh = 0; rh < 2; rh++) {
                    const int row = wr * 32 + s * 16 + lr + rh * 8;
                    const int e = tb + row;
                    const float2 p = *(const float2*)(psum + row * 2);
                    const float mu = p.x * (1.f / FD);
                    const float var = p.y * (1.f / FD) - mu * mu;
                    const float rs = rsqrtf(var + 1e-5f);
                    if (e < N_EDGES) {
#pragma unroll
                        for (int n = 0; n < 4; n++) {
                            const int f = wc * 32 + n * 8 + lq * 2;
                            float2 o;
                            o.x = (acc[s][n][rh * 2 + 0] - mu) * rs * gg[n].x + bb[n].x;
                            o.y = (acc[s][n][rh * 2 + 1] - mu) * rs * gg[n].y + bb[n].y;
                            *(float2*)(out + (size_t)e * FD + f) = o;
                        }
                    }
                }
        }
        // c==0's GBAR next tile separates psum reads from re-zero + atomics.
    }
}

// =====================================================================
// launch
// =====================================================================
extern "C" void kernel_launch(void* const* d_in, const int* in_sizes, int n_in,
                              void* d_out, int out_size) {
    const float* x  = (const float*)d_in[0];
    const int*   ei = (const int*)d_in[1];
    const float* ea = (const float*)d_in[2];
    const float* W  = (const float*)d_in[3];
    const float* b  = (const float*)d_in[4];
    const float* ng = (const float*)d_in[5];
    const float* nb = (const float*)d_in[6];
    const float* eg = (const float*)d_in[7];
    const float* eb = (const float*)d_in[8];
    float* out = (float*)d_out;

    prep_kernel<<<EA_BLOCKS + NODE_BLOCKS, 256>>>(x, ng, nb, ea);
    w_prep<<<NOUT, KDIM / 8>>>(W);

    cudaFuncSetAttribute(edge_kernel, cudaFuncAttributeMaxDynamicSharedMemorySize, SMEM_TOTAL);
    int nsm = 148;
    cudaDeviceGetAttribute(&nsm, cudaDevAttrMultiProcessorCount, 0);
    edge_kernel<<<nsm, 512, SMEM_TOTAL>>>(ei, b, eg, eb, out);
}

// round 7
// speedup vs baseline: 2.2830x; 1.0188x over previous
#include <cuda_runtime.h>
#include <cuda_fp16.h>
#include <cstdint>

// ---------------- problem constants ----------------
#define N_NODES 50000
#define N_EDGES 500000
#define FD      128
#define KDIM    384
#define NOUT    256
#define TILE_G  64                            // edges per warpgroup tile
#define NT_G    ((N_EDGES + TILE_G - 1) / TILE_G)   // 7813
#define EA_BLOCKS ((N_EDGES * FD) / 2048)     // 31250
#define NODE_BLOCKS ((N_NODES + 7) / 8)       // 6250

// ---------------- smem layout ----------------
#define B_OFF       0
#define B_BYTES     (6 * 32768)               // 6 K-blocks [256 n-rows x 64 halves], swizzled
#define A_OFF       B_BYTES                   // 196608
#define A_BUF_G     8192                      // one chunk [64 rows x 64 halves], swizzled
#define A_G_STRIDE  (2 * A_BUF_G)             // double buffer per group
#define IDX_OFF     (A_OFF + 2 * A_G_STRIDE)  // 229376 : per group src[64]+dst[64]
#define PSUM_OFF    (IDX_OFF + 1024)          // 230400 : per group 64 x (s,q) f32
#define SMEM_TOTAL  (PSUM_OFF + 1024)         // 231424 <= 232448

// ---------------- device scratch ----------------
__device__ __align__(256) __half        g_xn16[(size_t)N_NODES * FD];
__device__ __align__(256) __half        g_ea16[(size_t)N_EDGES * FD];
__device__ __align__(256) unsigned char g_wt16[B_BYTES];

// ---------------- ptx helpers ----------------
__device__ __forceinline__ uint32_t smem_u32(const void* p) {
    uint32_t a;
    asm("{ .reg .u64 t; cvta.to.shared.u64 t, %1; cvt.u32.u64 %0, t; }" : "=r"(a) : "l"(p));
    return a;
}
__device__ __forceinline__ void cpa16(uint32_t s, const void* g) {
    asm volatile("cp.async.cg.shared.global [%0], [%1], 16;" :: "r"(s), "l"(g));
}
#define CP_COMMIT() asm volatile("cp.async.commit_group;" ::: "memory")
#define CP_WAIT0()  asm volatile("cp.async.wait_group 0;" ::: "memory")
#define CP_WAIT1()  asm volatile("cp.async.wait_group 1;" ::: "memory")
#define GBAR(g)     asm volatile("bar.sync %0, 256;" :: "r"((g) + 1) : "memory")

__device__ __forceinline__ void ldsm4(uint32_t* r, uint32_t addr) {
    asm volatile("ldmatrix.sync.aligned.m8n8.x4.shared.b16 {%0,%1,%2,%3}, [%4];"
                 : "=r"(r[0]), "=r"(r[1]), "=r"(r[2]), "=r"(r[3]) : "r"(addr));
}
__device__ __forceinline__ void mma16816(float* c, const uint32_t* a, uint32_t b0, uint32_t b1) {
    asm volatile("mma.sync.aligned.m16n8k16.row.col.f32.f16.f16.f32 "
                 "{%0,%1,%2,%3}, {%4,%5,%6,%7}, {%8,%9}, {%0,%1,%2,%3};"
                 : "+f"(c[0]), "+f"(c[1]), "+f"(c[2]), "+f"(c[3])
                 : "r"(a[0]), "r"(a[1]), "r"(a[2]), "r"(a[3]), "r"(b0), "r"(b1));
}

// =====================================================================
// merged prep: ea f32->f16 stream + per-node LayerNorm + W convert
// =====================================================================
__global__ void prep_kernel(const float* __restrict__ x, const float* __restrict__ gma,
                            const float* __restrict__ bta, const float* __restrict__ ea,
                            const float* __restrict__ W) {
    if (blockIdx.x < EA_BLOCKS) {
        const size_t i = ((size_t)blockIdx.x * 256 + threadIdx.x) * 8;
        float4 f0 = *(const float4*)(ea + i);
        float4 f1 = *(const float4*)(ea + i + 4);
        union { __half2 h[4]; uint4 u; } o;
        o.h[0] = __floats2half2_rn(f0.x, f0.y);
        o.h[1] = __floats2half2_rn(f0.z, f0.w);
        o.h[2] = __floats2half2_rn(f1.x, f1.y);
        o.h[3] = __floats2half2_rn(f1.z, f1.w);
        *(uint4*)(g_ea16 + i) = o.u;
    } else if (blockIdx.x < EA_BLOCKS + NODE_BLOCKS) {
        const int wid = threadIdx.x >> 5, lane = threadIdx.x & 31;
        const int node = (blockIdx.x - EA_BLOCKS) * 8 + wid;
        if (node >= N_NODES) return;
        float4 v = *(const float4*)(x + (size_t)node * FD + lane * 4);
        float s = v.x + v.y + v.z + v.w;
        float q = v.x * v.x + v.y * v.y + v.z * v.z + v.w * v.w;
#pragma unroll
        for (int o = 16; o; o >>= 1) {
            s += __shfl_xor_sync(~0u, s, o);
            q += __shfl_xor_sync(~0u, q, o);
        }
        const float mu = s * (1.f / FD), var = q * (1.f / FD) - mu * mu;
        const float rs = rsqrtf(var + 1e-5f);
        float4 g = *(const float4*)(gma + lane * 4);
        float4 b = *(const float4*)(bta + lane * 4);
        union { __half2 h[2]; uint2 u; } o;
        o.h[0] = __floats2half2_rn((v.x - mu) * rs * g.x + b.x, (v.y - mu) * rs * g.y + b.y);
        o.h[1] = __floats2half2_rn((v.z - mu) * rs * g.z + b.z, (v.w - mu) * rs * g.w + b.w);
        *(uint2*)(g_xn16 + (size_t)node * FD + lane * 4) = o.u;
    } else {
        // W [K=384, N=256] f32 -> Wt blocks, column-permuted: strip wc holds
        // [delta f..f+31 | gate f..f+31], f = strip*32. XOR-swizzled.
        const int n = blockIdx.x - EA_BLOCKS - NODE_BLOCKS;   // 0..255
        const int t = threadIdx.x;
        if (t >= KDIM / 8) return;
        const int blkN = n >> 6, j = n & 63;
        const int f = blkN * 32 + (j & 31);
        const int src = (j < 32) ? f : (128 + f);
        const int k0 = t * 8;
        const int kb = k0 >> 6, kl = k0 & 63;
        union { __half h[8]; uint4 u; } pk;
#pragma unroll
        for (int i = 0; i < 8; i++) pk.h[i] = __float2half_rn(W[(k0 + i) * NOUT + src]);
        const uint32_t phys = kb * 32768 + n * 128 + ((((kl >> 3) ^ (n & 7))) << 4);
        *(uint4*)(g_wt16 + phys) = pk.u;
    }
}

// =====================================================================
// fused edge kernel — two independent 8-warp groups per CTA
// =====================================================================
__global__ void __launch_bounds__(512, 1)
edge_kernel(const int* __restrict__ ei, const float* __restrict__ bias,
            const float* __restrict__ eg, const float* __restrict__ eb,
            float* __restrict__ out) {
    extern __shared__ char smem[];
    const uint32_t sm_u = smem_u32(smem);
    const uint32_t bB = sm_u + B_OFF;

    const int tid  = threadIdx.x;
    const int g    = tid >> 8;            // warpgroup 0 / 1
    const int ltid = tid & 255;
    const int wid_g = ltid >> 5, lane = ltid & 31;
    const int wr = wid_g >> 2;            // 0..1 : rows wr*32..+31 of 64
    const int wc = wid_g & 3;             // 0..3 : permuted cols wc*64..+63
    const int row4 = ltid >> 2, q4 = ltid & 3;   // A build: 64 rows x 4 thr
    const int r7 = row4 & 7;
    const int lq = lane & 3, lr = lane >> 2;

    const uint32_t bA = sm_u + A_OFF + g * A_G_STRIDE;
    int*   s_src = (int*)(smem + IDX_OFF) + g * 128;
    int*   s_dst = s_src + 64;
    float* psum  = (float*)(smem + PSUM_OFF) + g * 128;

    // ---- stage resident B (all 512 threads) ----
    {
        const uint4* src = (const uint4*)g_wt16;
        uint4* dst = (uint4*)(smem + B_OFF);
        for (int i = tid; i < B_BYTES / 16; i += 512) dst[i] = src[i];
    }

    // ---- ldmatrix lane addressing ----
    const int li = lane & 7, lgrp = lane >> 3;
    uint32_t a_off[2]; int a_r7[2];
#pragma unroll
    for (int s = 0; s < 2; s++) {
        const int row = wr * 32 + s * 16 + li + (lgrp & 1) * 8;
        a_off[s] = row * 128;
        a_r7[s] = row & 7;
    }
    const int a_qb = lgrp >> 1;
    uint32_t b_off[4]; int b_r7[4];
#pragma unroll
    for (int j = 0; j < 4; j++) {
        const int rn = wc * 64 + j * 16 + li + (lgrp >> 1) * 8;
        b_off[j] = rn * 128;
        b_r7[j] = rn & 7;
    }
    const int b_qb = lgrp & 1;

    const uint32_t d_off0 = row4 * 128 + (((2 * q4) ^ r7) << 4);
    const uint32_t d_off1 = row4 * 128 + (((2 * q4 + 1) ^ r7) << 4);

    // residual read base: feats 0-63 live in buf0 (chunk4), 64-127 in buf1 (chunk5)
    const uint32_t res_base = bA + (wc >> 1) * A_BUF_G;

    __syncthreads();   // B visible to both groups; last CTA-wide barrier

    // ---- group prologue: first tile idx + psum ----
    const int t0 = blockIdx.x * 2 + g;
    const int tstride = gridDim.x * 2;
    {
        const int tb0 = t0 * TILE_G;
        if (ltid < 64) {
            const int e = tb0 + ltid;
            s_src[ltid] = (e < N_EDGES) ? ei[e] : 0;
        } else if (ltid < 128) {
            const int e = tb0 + ltid - 64;
            s_dst[ltid - 64] = (e < N_EDGES) ? ei[N_EDGES + e] : 0;
        } else {
            psum[ltid - 128] = 0.f;
        }
    }

    for (int t = t0; t < NT_G; t += tstride) {
        const int tb = t * TILE_G;
        const int er = min(tb + row4, N_EDGES - 1);

        float acc[2][8][4];
#pragma unroll
        for (int s = 0; s < 2; s++)
#pragma unroll
            for (int n = 0; n < 8; n++)
#pragma unroll
                for (int i = 0; i < 4; i++) acc[s][n][i] = 0.f;

        // ---- 6 chunks of K=64 ----
#pragma unroll 1
        for (int c = 0; c < 6; c++) {
            if (c > 0) CP_WAIT0();
            GBAR(g);   // c==0: orders epilogue residual reads + psum before reuse

            if (c == 0) {
                if (ltid >= 128) psum[ltid - 128] = 0.f;
                // issue gather for chunk 0 (buf0)
                const char* gp = (const char*)(g_xn16 + (size_t)s_src[row4] * FD) + q4 * 32;
                cpa16(bA + d_off0, gp);
                cpa16(bA + d_off1, gp + 16);
                CP_COMMIT();
            } else if (c == 3) {
                // stage NEXT tile's indices (last gather using idx was issued at c==2)
                const int tn = t + tstride;
                const int tbn = tn * TILE_G;
                if (ltid < 64) {
                    const int e = tbn + ltid;
                    s_src[ltid] = (tn < NT_G && e < N_EDGES) ? ei[e] : 0;
                } else if (ltid < 128) {
                    const int e = tbn + ltid - 64;
                    s_dst[ltid - 64] = (tn < NT_G && e < N_EDGES) ? ei[N_EDGES + e] : 0;
                }
            }

            // issue gather for chunk c+1 into buf (c+1)&1
            if (c < 5) {
                const char* gp;
                if (c == 0)      gp = (const char*)(g_xn16 + (size_t)s_src[row4] * FD + 64);
                else if (c == 1) gp = (const char*)(g_xn16 + (size_t)s_dst[row4] * FD);
                else if (c == 2) gp = (const char*)(g_xn16 + (size_t)s_dst[row4] * FD + 64);
                else if (c == 3) gp = (const char*)(g_ea16 + (size_t)er * FD);
                else             gp = (const char*)(g_ea16 + (size_t)er * FD + 64);
                const uint32_t db = bA + ((c + 1) & 1) * A_BUF_G;
                cpa16(db + d_off0, gp + q4 * 32);
                cpa16(db + d_off1, gp + q4 * 32 + 16);
                CP_COMMIT();
            }

            if (c == 0) {
                CP_WAIT1();   // chunk 0 landed (chunk 1 may still be in flight)
                GBAR(g);      // visibility of chunk 0 across the group
            }

            // MMA on chunk c (buf c&1)
            const uint32_t abuf = bA + (c & 1) * A_BUF_G;
            const uint32_t bblk = bB + c * 32768;
#pragma unroll
            for (int ks = 0; ks < 4; ks++) {
                uint32_t A[2][4];
#pragma unroll
                for (int s = 0; s < 2; s++)
                    ldsm4(A[s], abuf + a_off[s] + ((((2 * ks + a_qb) ^ a_r7[s])) << 4));
                uint32_t Bv[4][4];
#pragma unroll
                for (int j = 0; j < 4; j++)
                    ldsm4(Bv[j], bblk + b_off[j] + ((((2 * ks + b_qb) ^ b_r7[j])) << 4));
#pragma unroll
                for (int s = 0; s < 2; s++)
#pragma unroll
                    for (int j = 0; j < 4; j++) {
                        mma16816(acc[s][2 * j],     A[s], Bv[j][0], Bv[j][1]);
                        mma16816(acc[s][2 * j + 1], A[s], Bv[j][2], Bv[j][3]);
                    }
            }
        }
        // chunk4 (ea feats 0-63, buf0) and chunk5 (feats 64-127, buf1) survive.

        // ---- epilogue part 1: gated residual (residual via LDS) + partials ----
        {
            float srs[4], qrs[4];
#pragma unroll
            for (int ri = 0; ri < 4; ri++) { srs[ri] = 0.f; qrs[ri] = 0.f; }

#pragma unroll
            for (int n = 0; n < 4; n++) {
                const int f = wc * 32 + n * 8 + lq * 2;
                const float2 bd = __ldg((const float2*)(bias + f));
                const float2 bg = __ldg((const float2*)(bias + 128 + f));
                const uint32_t colb = (wc & 1) * 64 + n * 16 + lq * 4;
                const uint32_t xorterm = (((colb >> 4) ^ (uint32_t)lr) << 4) + (colb & 15);
#pragma unroll
                for (int s = 0; s < 2; s++)
#pragma unroll
                    for (int rh = 0; rh < 2; rh++) {
                        const int ri = s * 2 + rh;
                        const int row = wr * 32 + s * 16 + rh * 8 + lr;
                        uint32_t ru;
                        asm volatile("ld.shared.b32 %0, [%1];"
                                     : "=r"(ru) : "r"(res_base + row * 128 + xorterm));
                        const float2 res = __half22float2(*(__half2*)&ru);
                        float d0 = fmaxf(acc[s][n][rh * 2 + 0] + bd.x, 0.f);
                        float d1 = fmaxf(acc[s][n][rh * 2 + 1] + bd.y, 0.f);
                        float g0 = fmaxf(acc[s][n + 4][rh * 2 + 0] + bg.x, 0.f);
                        float g1 = fmaxf(acc[s][n + 4][rh * 2 + 1] + bg.y, 0.f);
                        float s0 = __frcp_rn(1.f + __expf(-g0));
                        float s1 = __frcp_rn(1.f + __expf(-g1));
                        float v0 = fmaf(d0, s0, res.x);
                        float v1 = fmaf(d1, s1, res.y);
                        acc[s][n][rh * 2 + 0] = v0;
                        acc[s][n][rh * 2 + 1] = v1;
                        srs[ri] += v0 + v1;
                        qrs[ri] = fmaf(v0, v0, fmaf(v1, v1, qrs[ri]));
                    }
            }
#pragma unroll
            for (int ri = 0; ri < 4; ri++) {
                float s_ = srs[ri], q_ = qrs[ri];
                s_ += __shfl_xor_sync(~0u, s_, 1);
                q_ += __shfl_xor_sync(~0u, q_, 1);
                s_ += __shfl_xor_sync(~0u, s_, 2);
                q_ += __shfl_xor_sync(~0u, q_, 2);
                if (lq == 0) {
                    const int row = wr * 32 + (ri >> 1) * 16 + lr + (ri & 1) * 8;
                    atomicAdd(&psum[row * 2],     s_);
                    atomicAdd(&psum[row * 2 + 1], q_);
                }
            }
        }
        GBAR(g);

        // ---- epilogue part 2: LayerNorm + store ----
        {
            float2 gg[4], bb[4];
#pragma unroll
            for (int n = 0; n < 4; n++) {
                const int f = wc * 32 + n * 8 + lq * 2;
                gg[n] = __ldg((const float2*)(eg + f));
                bb[n] = __ldg((const float2*)(eb + f));
            }
#pragma unroll
            for (int s = 0; s < 2; s++)
#pragma unroll
                for (int rh = 0; rh < 2; rh++) {
                    const int row = wr * 32 + s * 16 + lr + rh * 8;
                    const int e = tb + row;
                    const float2 p = *(const float2*)(psum + row * 2);
                    const float mu = p.x * (1.f / FD);
                    const float var = p.y * (1.f / FD) - mu * mu;
                    const float rs = rsqrtf(var + 1e-5f);
                    if (e < N_EDGES) {
#pragma unroll
                        for (int n = 0; n < 4; n++) {
                            const int f = wc * 32 + n * 8 + lq * 2;
                            float2 o;
                            o.x = (acc[s][n][rh * 2 + 0] - mu) * rs * gg[n].x + bb[n].x;
                            o.y = (acc[s][n][rh * 2 + 1] - mu) * rs * gg[n].y + bb[n].y;
                            *(float2*)(out + (size_t)e * FD + f) = o;
                        }
                    }
                }
        }
        // next tile's c==0 GBAR orders psum reads / residual reads before reuse.
    }
}

// =====================================================================
// launch
// =====================================================================
extern "C" void kernel_launch(void* const* d_in, const int* in_sizes, int n_in,
                              void* d_out, int out_size) {
    const float* x  = (const float*)d_in[0];
    const int*   ei = (const int*)d_in[1];
    const float* ea = (const float*)d_in[2];
    const float* W  = (const float*)d_in[3];
    const float* b  = (const float*)d_in[4];
    const float* ng = (const float*)d_in[5];
    const float* nb = (const float*)d_in[6];
    const float* eg = (const float*)d_in[7];
    const float* eb = (const float*)d_in[8];
    float* out = (float*)d_out;

    prep_kernel<<<EA_BLOCKS + NODE_BLOCKS + NOUT, 256>>>(x, ng, nb, ea, W);

    cudaFuncSetAttribute(edge_kernel, cudaFuncAttributeMaxDynamicSharedMemorySize, SMEM_TOTAL);
    int nsm = 148;
    cudaDeviceGetAttribute(&nsm, cudaDevAttrMultiProcessorCount, 0);
    edge_kernel<<<nsm, 512, SMEM_TOTAL>>>(ei, b, eg, eb, out);
}

// round 8
// speedup vs baseline: 2.3876x; 1.0458x over previous
#include <cuda_runtime.h>
#include <cuda_fp16.h>
#include <cstdint>

// ---------------- problem constants ----------------
#define N_NODES 50000
#define N_EDGES 500000
#define FD      128
#define KDIM    384
#define NOUT    256
#define TILE_G  32                            // edges per group tile
#define NT_G    (N_EDGES / TILE_G)            // 15625 (exact)
#define NGROUP  4
#define EA_BLOCKS ((N_EDGES * FD) / 2048)     // 31250
#define NODE_BLOCKS ((N_NODES + 7) / 8)       // 6250

// ---------------- smem layout ----------------
#define B_OFF       0
#define B_BYTES     (6 * 32768)               // 6 K-blocks [256 n-rows x 64 halves], swizzled
#define A_OFF       B_BYTES                   // 196608
#define A_BUF_G     4096                      // one chunk [32 rows x 64 halves], swizzled
#define A_G_STRIDE  (2 * A_BUF_G)             // double buffer per group
#define IDX_OFF     (A_OFF + NGROUP * A_G_STRIDE)  // 229376 : per group src[32]+dst[32]
#define PSUM_OFF    (IDX_OFF + 1024)          // 230400 : per group 32 x (s,q) f32
#define SMEM_TOTAL  (PSUM_OFF + 1024)         // 231424 <= 232448

// ---------------- device scratch ----------------
__device__ __align__(256) __half        g_xn16[(size_t)N_NODES * FD];
__device__ __align__(256) __half        g_ea16[(size_t)N_EDGES * FD];
__device__ __align__(256) unsigned char g_wt16[B_BYTES];

// ---------------- ptx helpers ----------------
__device__ __forceinline__ uint32_t smem_u32(const void* p) {
    uint32_t a;
    asm("{ .reg .u64 t; cvta.to.shared.u64 t, %1; cvt.u32.u64 %0, t; }" : "=r"(a) : "l"(p));
    return a;
}
__device__ __forceinline__ void cpa16(uint32_t s, const void* g) {
    asm volatile("cp.async.cg.shared.global [%0], [%1], 16;" :: "r"(s), "l"(g));
}
#define CP_COMMIT() asm volatile("cp.async.commit_group;" ::: "memory")
#define CP_WAIT0()  asm volatile("cp.async.wait_group 0;" ::: "memory")
#define GBAR(g)     asm volatile("bar.sync %0, 128;" :: "r"((g) + 1) : "memory")

__device__ __forceinline__ void ldsm4(uint32_t* r, uint32_t addr) {
    asm volatile("ldmatrix.sync.aligned.m8n8.x4.shared.b16 {%0,%1,%2,%3}, [%4];"
                 : "=r"(r[0]), "=r"(r[1]), "=r"(r[2]), "=r"(r[3]) : "r"(addr));
}
__device__ __forceinline__ void mma16816(float* c, const uint32_t* a, uint32_t b0, uint32_t b1) {
    asm volatile("mma.sync.aligned.m16n8k16.row.col.f32.f16.f16.f32 "
                 "{%0,%1,%2,%3}, {%4,%5,%6,%7}, {%8,%9}, {%0,%1,%2,%3};"
                 : "+f"(c[0]), "+f"(c[1]), "+f"(c[2]), "+f"(c[3])
                 : "r"(a[0]), "r"(a[1]), "r"(a[2]), "r"(a[3]), "r"(b0), "r"(b1));
}

// =====================================================================
// merged prep: ea f32->f16 stream + per-node LayerNorm + W convert
// =====================================================================
__global__ void prep_kernel(const float* __restrict__ x, const float* __restrict__ gma,
                            const float* __restrict__ bta, const float* __restrict__ ea,
                            const float* __restrict__ W) {
    if (blockIdx.x < EA_BLOCKS) {
        const size_t i = ((size_t)blockIdx.x * 256 + threadIdx.x) * 8;
        float4 f0 = *(const float4*)(ea + i);
        float4 f1 = *(const float4*)(ea + i + 4);
        union { __half2 h[4]; uint4 u; } o;
        o.h[0] = __floats2half2_rn(f0.x, f0.y);
        o.h[1] = __floats2half2_rn(f0.z, f0.w);
        o.h[2] = __floats2half2_rn(f1.x, f1.y);
        o.h[3] = __floats2half2_rn(f1.z, f1.w);
        *(uint4*)(g_ea16 + i) = o.u;
    } else if (blockIdx.x < EA_BLOCKS + NODE_BLOCKS) {
        const int wid = threadIdx.x >> 5, lane = threadIdx.x & 31;
        const int node = (blockIdx.x - EA_BLOCKS) * 8 + wid;
        if (node >= N_NODES) return;
        float4 v = *(const float4*)(x + (size_t)node * FD + lane * 4);
        float s = v.x + v.y + v.z + v.w;
        float q = v.x * v.x + v.y * v.y + v.z * v.z + v.w * v.w;
#pragma unroll
        for (int o = 16; o; o >>= 1) {
            s += __shfl_xor_sync(~0u, s, o);
            q += __shfl_xor_sync(~0u, q, o);
        }
        const float mu = s * (1.f / FD), var = q * (1.f / FD) - mu * mu;
        const float rs = rsqrtf(var + 1e-5f);
        float4 g = *(const float4*)(gma + lane * 4);
        float4 b = *(const float4*)(bta + lane * 4);
        union { __half2 h[2]; uint2 u; } o;
        o.h[0] = __floats2half2_rn((v.x - mu) * rs * g.x + b.x, (v.y - mu) * rs * g.y + b.y);
        o.h[1] = __floats2half2_rn((v.z - mu) * rs * g.z + b.z, (v.w - mu) * rs * g.w + b.w);
        *(uint2*)(g_xn16 + (size_t)node * FD + lane * 4) = o.u;
    } else {
        // W -> Wt blocks, column-permuted: strip wc = [delta f..f+31 | gate f..f+31]
        const int n = blockIdx.x - EA_BLOCKS - NODE_BLOCKS;   // 0..255
        const int t = threadIdx.x;
        if (t >= KDIM / 8) return;
        const int blkN = n >> 6, j = n & 63;
        const int f = blkN * 32 + (j & 31);
        const int src = (j < 32) ? f : (128 + f);
        const int k0 = t * 8;
        const int kb = k0 >> 6, kl = k0 & 63;
        union { __half h[8]; uint4 u; } pk;
#pragma unroll
        for (int i = 0; i < 8; i++) pk.h[i] = __float2half_rn(W[(k0 + i) * NOUT + src]);
        const uint32_t phys = kb * 32768 + n * 128 + ((((kl >> 3) ^ (n & 7))) << 4);
        *(uint4*)(g_wt16 + phys) = pk.u;
    }
}

// =====================================================================
// fused edge kernel — four independent 4-warp groups per CTA
// =====================================================================
__global__ void __launch_bounds__(512, 1)
edge_kernel(const int* __restrict__ ei, const float* __restrict__ bias,
            const float* __restrict__ eg, const float* __restrict__ eb,
            float* __restrict__ out) {
    extern __shared__ char smem[];
    const uint32_t sm_u = smem_u32(smem);
    const uint32_t bB = sm_u + B_OFF;

    const int tid  = threadIdx.x;
    const int g    = tid >> 7;            // group 0..3
    const int ltid = tid & 127;
    const int wc   = ltid >> 5;           // 0..3 : permuted cols wc*64..+63
    const int lane = ltid & 31;
    const int row2 = ltid >> 2, q4 = ltid & 3;   // A build: 32 rows x 4 thr
    const int r7 = row2 & 7;
    const int lq = lane & 3, lr = lane >> 2;

    const uint32_t bA = sm_u + A_OFF + g * A_G_STRIDE;
    int*   s_src = (int*)(smem + IDX_OFF) + g * 64;
    int*   s_dst = s_src + 32;
    float* psum  = (float*)(smem + PSUM_OFF) + g * 64;

    // ---- stage resident B (all 512 threads) ----
    {
        const uint4* src = (const uint4*)g_wt16;
        uint4* dst = (uint4*)(smem + B_OFF);
        for (int i = tid; i < B_BYTES / 16; i += 512) dst[i] = src[i];
    }

    // ---- ldmatrix lane addressing ----
    const int li = lane & 7, lgrp = lane >> 3;
    uint32_t a_off[2]; int a_r7[2];
#pragma unroll
    for (int s = 0; s < 2; s++) {
        const int row = s * 16 + li + (lgrp & 1) * 8;
        a_off[s] = row * 128;
        a_r7[s] = row & 7;
    }
    const int a_qb = lgrp >> 1;
    uint32_t b_off[4]; int b_r7[4];
#pragma unroll
    for (int j = 0; j < 4; j++) {
        const int rn = wc * 64 + j * 16 + li + (lgrp >> 1) * 8;
        b_off[j] = rn * 128;
        b_r7[j] = rn & 7;
    }
    const int b_qb = lgrp & 1;

    const uint32_t d_off0 = row2 * 128 + (((2 * q4) ^ r7) << 4);
    const uint32_t d_off1 = row2 * 128 + (((2 * q4 + 1) ^ r7) << 4);

    // residual base: feats 0-63 in buf0 (chunk4), 64-127 in buf1 (chunk5)
    const uint32_t res_base = bA + (wc >> 1) * A_BUF_G;

    __syncthreads();   // B visible; last CTA-wide barrier

    const int t0 = blockIdx.x * NGROUP + g;
    const int tstride = gridDim.x * NGROUP;

    // ---- group prologue: first tile idx + psum, then chunk-0 gather ----
    if (t0 < NT_G) {
        const int tb0 = t0 * TILE_G;
        if (ltid < 32)       s_src[ltid] = ei[tb0 + ltid];
        else if (ltid < 64)  s_dst[ltid - 32] = ei[N_EDGES + tb0 + ltid - 32];
        else                 psum[ltid - 64] = 0.f;
    }
    GBAR(g);
    if (t0 < NT_G) {
        const char* gp = (const char*)(g_xn16 + (size_t)s_src[row2] * FD) + q4 * 32;
        cpa16(bA + d_off0, gp);
        cpa16(bA + d_off1, gp + 16);
        CP_COMMIT();
    }

    for (int t = t0; t < NT_G; t += tstride) {
        const int tb = t * TILE_G;
        const int er = tb + row2;
        const bool more = (t + tstride) < NT_G;

        float acc[2][8][4];
#pragma unroll
        for (int s = 0; s < 2; s++)
#pragma unroll
            for (int n = 0; n < 8; n++)
#pragma unroll
                for (int i = 0; i < 4; i++) acc[s][n][i] = 0.f;

        // ---- 6 chunks of K=64 (chunk c's gather issued one step ahead) ----
#pragma unroll 1
        for (int c = 0; c < 6; c++) {
            CP_WAIT0();
            GBAR(g);

            if (c == 0) {
                if (ltid >= 64) psum[ltid - 64] = 0.f;
            } else if (c == 3 && more) {
                const int tbn = (t + tstride) * TILE_G;
                if (ltid < 32)      s_src[ltid] = ei[tbn + ltid];
                else if (ltid < 64) s_dst[ltid - 32] = ei[N_EDGES + tbn + ltid - 32];
            }

            if (c < 5) {
                const char* gp;
                if (c == 0)      gp = (const char*)(g_xn16 + (size_t)s_src[row2] * FD + 64);
                else if (c == 1) gp = (const char*)(g_xn16 + (size_t)s_dst[row2] * FD);
                else if (c == 2) gp = (const char*)(g_xn16 + (size_t)s_dst[row2] * FD + 64);
                else if (c == 3) gp = (const char*)(g_ea16 + (size_t)er * FD);
                else             gp = (const char*)(g_ea16 + (size_t)er * FD + 64);
                const uint32_t db = bA + ((c + 1) & 1) * A_BUF_G;
                cpa16(db + d_off0, gp + q4 * 32);
                cpa16(db + d_off1, gp + q4 * 32 + 16);
                CP_COMMIT();
            }

            // MMA on chunk c (buf c&1)
            const uint32_t abuf = bA + (c & 1) * A_BUF_G;
            const uint32_t bblk = bB + c * 32768;
#pragma unroll
            for (int ks = 0; ks < 4; ks++) {
                uint32_t A[2][4];
#pragma unroll
                for (int s = 0; s < 2; s++)
                    ldsm4(A[s], abuf + a_off[s] + ((((2 * ks + a_qb) ^ a_r7[s])) << 4));
                uint32_t Bv[4][4];
#pragma unroll
                for (int j = 0; j < 4; j++)
                    ldsm4(Bv[j], bblk + b_off[j] + ((((2 * ks + b_qb) ^ b_r7[j])) << 4));
#pragma unroll
                for (int s = 0; s < 2; s++)
#pragma unroll
                    for (int j = 0; j < 4; j++) {
                        mma16816(acc[s][2 * j],     A[s], Bv[j][0], Bv[j][1]);
                        mma16816(acc[s][2 * j + 1], A[s], Bv[j][2], Bv[j][3]);
                    }
            }
        }
        // chunk4 (ea feats 0-63, buf0) and chunk5 (feats 64-127, buf1) survive.

        // ---- epilogue part 1: gated residual (residual via LDS) + partials ----
        {
            float srs[4], qrs[4];
#pragma unroll
            for (int ri = 0; ri < 4; ri++) { srs[ri] = 0.f; qrs[ri] = 0.f; }

#pragma unroll
            for (int n = 0; n < 4; n++) {
                const int f = wc * 32 + n * 8 + lq * 2;
                const float2 bd = __ldg((const float2*)(bias + f));
                const float2 bg = __ldg((const float2*)(bias + 128 + f));
                const uint32_t colb = (wc & 1) * 64 + n * 16 + lq * 4;
                const uint32_t xorterm = (((colb >> 4) ^ (uint32_t)lr) << 4) + (colb & 15);
#pragma unroll
                for (int s = 0; s < 2; s++)
#pragma unroll
                    for (int rh = 0; rh < 2; rh++) {
                        const int ri = s * 2 + rh;
                        const int row = s * 16 + rh * 8 + lr;
                        uint32_t ru;
                        asm volatile("ld.shared.b32 %0, [%1];"
                                     : "=r"(ru) : "r"(res_base + row * 128 + xorterm));
                        const float2 res = __half22float2(*(__half2*)&ru);
                        float d0 = fmaxf(acc[s][n][rh * 2 + 0] + bd.x, 0.f);
                        float d1 = fmaxf(acc[s][n][rh * 2 + 1] + bd.y, 0.f);
                        float g0 = fmaxf(acc[s][n + 4][rh * 2 + 0] + bg.x, 0.f);
                        float g1 = fmaxf(acc[s][n + 4][rh * 2 + 1] + bg.y, 0.f);
                        float s0 = __frcp_rn(1.f + __expf(-g0));
                        float s1 = __frcp_rn(1.f + __expf(-g1));
                        float v0 = fmaf(d0, s0, res.x);
                        float v1 = fmaf(d1, s1, res.y);
                        acc[s][n][rh * 2 + 0] = v0;
                        acc[s][n][rh * 2 + 1] = v1;
                        srs[ri] += v0 + v1;
                        qrs[ri] = fmaf(v0, v0, fmaf(v1, v1, qrs[ri]));
                    }
            }
#pragma unroll
            for (int ri = 0; ri < 4; ri++) {
                float s_ = srs[ri], q_ = qrs[ri];
                s_ += __shfl_xor_sync(~0u, s_, 1);
                q_ += __shfl_xor_sync(~0u, q_, 1);
                s_ += __shfl_xor_sync(~0u, s_, 2);
                q_ += __shfl_xor_sync(~0u, q_, 2);
                if (lq == 0) {
                    const int row = (ri >> 1) * 16 + (ri & 1) * 8 + lr;
                    atomicAdd(&psum[row * 2],     s_);
                    atomicAdd(&psum[row * 2 + 1], q_);
                }
            }
        }
        GBAR(g);

        // ---- overlap: issue NEXT tile's chunk-0 gather (idx staged at c==3) ----
        if (more) {
            const char* gp = (const char*)(g_xn16 + (size_t)s_src[row2] * FD) + q4 * 32;
            cpa16(bA + d_off0, gp);
            cpa16(bA + d_off1, gp + 16);
            CP_COMMIT();
        }

        // ---- epilogue part 2: LayerNorm + store ----
        {
            float2 gg[4], bb[4];
#pragma unroll
            for (int n = 0; n < 4; n++) {
                const int f = wc * 32 + n * 8 + lq * 2;
                gg[n] = __ldg((const float2*)(eg + f));
                bb[n] = __ldg((const float2*)(eb + f));
            }
#pragma unroll
            for (int s = 0; s < 2; s++)
#pragma unroll
                for (int rh = 0; rh < 2; rh++) {
                    const int row = s * 16 + rh * 8 + lr;
                    const int e = tb + row;
                    const float2 p = *(const float2*)(psum + row * 2);
                    const float mu = p.x * (1.f / FD);
                    const float var = p.y * (1.f / FD) - mu * mu;
                    const float rs = rsqrtf(var + 1e-5f);
#pragma unroll
                    for (int n = 0; n < 4; n++) {
                        const int f = wc * 32 + n * 8 + lq * 2;
                        float2 o;
                        o.x = (acc[s][n][rh * 2 + 0] - mu) * rs * gg[n].x + bb[n].x;
                        o.y = (acc[s][n][rh * 2 + 1] - mu) * rs * gg[n].y + bb[n].y;
                        *(float2*)(out + (size_t)e * FD + f) = o;
                    }
                }
        }
        // next tile's c==0 GBAR orders psum reads before re-zero/atomics.
    }
}

// =====================================================================
// launch
// =====================================================================
extern "C" void kernel_launch(void* const* d_in, const int* in_sizes, int n_in,
                              void* d_out, int out_size) {
    const float* x  = (const float*)d_in[0];
    const int*   ei = (const int*)d_in[1];
    const float* ea = (const float*)d_in[2];
    const float* W  = (const float*)d_in[3];
    const float* b  = (const float*)d_in[4];
    const float* ng = (const float*)d_in[5];
    const float* nb = (const float*)d_in[6];
    const float* eg = (const float*)d_in[7];
    const float* eb = (const float*)d_in[8];
    float* out = (float*)d_out;

    prep_kernel<<<EA_BLOCKS + NODE_BLOCKS + NOUT, 256>>>(x, ng, nb, ea, W);

    cudaFuncSetAttribute(edge_kernel, cudaFuncAttributeMaxDynamicSharedMemorySize, SMEM_TOTAL);
    int nsm = 148;
    cudaDeviceGetAttribute(&nsm, cudaDevAttrMultiProcessorCount, 0);
    edge_kernel<<<nsm, 512, SMEM_TOTAL>>>(ei, b, eg, eb, out);
}

// round 9
// speedup vs baseline: 2.4807x; 1.0390x over previous
#include <cuda_runtime.h>
#include <cuda_fp16.h>
#include <cstdint>

// ---------------- problem constants ----------------
#define N_NODES 50000
#define N_EDGES 500000
#define FD      128
#define KDIM    384
#define NOUT    256
#define TILE_G  32                            // edges per group tile
#define NT_G    (N_EDGES / TILE_G)            // 15625 (exact)
#define NGROUP  4
#define NODE_BLOCKS ((N_NODES + 7) / 8)       // 6250

// ---------------- smem layout ----------------
#define B_OFF       0
#define B_BYTES     (6 * 32768)               // 6 K-blocks [256 n-rows x 64 halves], swizzled
#define A_OFF       B_BYTES                   // 196608
#define A_BUF_G     4096                      // one chunk [32 rows x 64 halves], swizzled
#define A_G_STRIDE  (2 * A_BUF_G)             // double buffer per group
#define IDX_OFF     (A_OFF + NGROUP * A_G_STRIDE)  // 229376 : per group src[32]+dst[32]
#define PSUM_OFF    (IDX_OFF + 1024)          // 230400 : per group 32 x (s,q) f32
#define SMEM_TOTAL  (PSUM_OFF + 1024)         // 231424 <= 232448

// ---------------- device scratch ----------------
__device__ __align__(256) __half        g_xn16[(size_t)N_NODES * FD];
__device__ __align__(256) unsigned char g_wt16[B_BYTES];

// ---------------- ptx helpers ----------------
__device__ __forceinline__ uint32_t smem_u32(const void* p) {
    uint32_t a;
    asm("{ .reg .u64 t; cvta.to.shared.u64 t, %1; cvt.u32.u64 %0, t; }" : "=r"(a) : "l"(p));
    return a;
}
__device__ __forceinline__ void cpa16(uint32_t s, const void* g) {
    asm volatile("cp.async.cg.shared.global [%0], [%1], 16;" :: "r"(s), "l"(g));
}
#define CP_COMMIT() asm volatile("cp.async.commit_group;" ::: "memory")
#define CP_WAIT0()  asm volatile("cp.async.wait_group 0;" ::: "memory")
#define GBAR(g)     asm volatile("bar.sync %0, 128;" :: "r"((g) + 1) : "memory")

__device__ __forceinline__ void ldsm4(uint32_t* r, uint32_t addr) {
    asm volatile("ldmatrix.sync.aligned.m8n8.x4.shared.b16 {%0,%1,%2,%3}, [%4];"
                 : "=r"(r[0]), "=r"(r[1]), "=r"(r[2]), "=r"(r[3]) : "r"(addr));
}
__device__ __forceinline__ void mma16816(float* c, const uint32_t* a, uint32_t b0, uint32_t b1) {
    asm volatile("mma.sync.aligned.m16n8k16.row.col.f32.f16.f16.f32 "
                 "{%0,%1,%2,%3}, {%4,%5,%6,%7}, {%8,%9}, {%0,%1,%2,%3};"
                 : "+f"(c[0]), "+f"(c[1]), "+f"(c[2]), "+f"(c[3])
                 : "r"(a[0]), "r"(a[1]), "r"(a[2]), "r"(a[3]), "r"(b0), "r"(b1));
}
__device__ __forceinline__ void sts16(uint32_t addr, uint4 v) {
    asm volatile("st.shared.v4.b32 [%0], {%1,%2,%3,%4};"
                 :: "r"(addr), "r"(v.x), "r"(v.y), "r"(v.z), "r"(v.w) : "memory");
}
__device__ __forceinline__ uint4 pack8h(float4 a, float4 b) {
    union { __half2 h[4]; uint4 u; } o;
    o.h[0] = __floats2half2_rn(a.x, a.y);
    o.h[1] = __floats2half2_rn(a.z, a.w);
    o.h[2] = __floats2half2_rn(b.x, b.y);
    o.h[3] = __floats2half2_rn(b.z, b.w);
    return o.u;
}

// =====================================================================
// prep: per-node LayerNorm -> f16, plus W convert/permute/swizzle
// =====================================================================
__global__ void prep_kernel(const float* __restrict__ x, const float* __restrict__ gma,
                            const float* __restrict__ bta, const float* __restrict__ W) {
    if (blockIdx.x < NODE_BLOCKS) {
        const int wid = threadIdx.x >> 5, lane = threadIdx.x & 31;
        const int node = blockIdx.x * 8 + wid;
        if (node >= N_NODES) return;
        float4 v = *(const float4*)(x + (size_t)node * FD + lane * 4);
        float s = v.x + v.y + v.z + v.w;
        float q = v.x * v.x + v.y * v.y + v.z * v.z + v.w * v.w;
#pragma unroll
        for (int o = 16; o; o >>= 1) {
            s += __shfl_xor_sync(~0u, s, o);
            q += __shfl_xor_sync(~0u, q, o);
        }
        const float mu = s * (1.f / FD), var = q * (1.f / FD) - mu * mu;
        const float rs = rsqrtf(var + 1e-5f);
        float4 g = *(const float4*)(gma + lane * 4);
        float4 b = *(const float4*)(bta + lane * 4);
        union { __half2 h[2]; uint2 u; } o;
        o.h[0] = __floats2half2_rn((v.x - mu) * rs * g.x + b.x, (v.y - mu) * rs * g.y + b.y);
        o.h[1] = __floats2half2_rn((v.z - mu) * rs * g.z + b.z, (v.w - mu) * rs * g.w + b.w);
        *(uint2*)(g_xn16 + (size_t)node * FD + lane * 4) = o.u;
    } else {
        // W -> Wt blocks, column-permuted: strip wc = [delta f..f+31 | gate f..f+31]
        const int n = blockIdx.x - NODE_BLOCKS;   // 0..255
        const int t = threadIdx.x;
        if (t >= KDIM / 8) return;
        const int blkN = n >> 6, j = n & 63;
        const int f = blkN * 32 + (j & 31);
        const int src = (j < 32) ? f : (128 + f);
        const int k0 = t * 8;
        const int kb = k0 >> 6, kl = k0 & 63;
        union { __half h[8]; uint4 u; } pk;
#pragma unroll
        for (int i = 0; i < 8; i++) pk.h[i] = __float2half_rn(W[(k0 + i) * NOUT + src]);
        const uint32_t phys = kb * 32768 + n * 128 + ((((kl >> 3) ^ (n & 7))) << 4);
        *(uint4*)(g_wt16 + phys) = pk.u;
    }
}

// =====================================================================
// fused edge kernel — four independent 4-warp groups per CTA
// ea f32 converted in-kernel (chunks 4/5), no g_ea16 intermediate
// =====================================================================
__global__ void __launch_bounds__(512, 1)
edge_kernel(const int* __restrict__ ei, const float* __restrict__ ea,
            const float* __restrict__ bias, const float* __restrict__ eg,
            const float* __restrict__ eb, float* __restrict__ out) {
    extern __shared__ char smem[];
    const uint32_t sm_u = smem_u32(smem);
    const uint32_t bB = sm_u + B_OFF;

    const int tid  = threadIdx.x;
    const int g    = tid >> 7;            // group 0..3
    const int ltid = tid & 127;
    const int wc   = ltid >> 5;           // 0..3 : permuted cols wc*64..+63
    const int lane = ltid & 31;
    const int row2 = ltid >> 2, q4 = ltid & 3;   // A build: 32 rows x 4 thr
    const int r7 = row2 & 7;
    const int lq = lane & 3, lr = lane >> 2;

    const uint32_t bA = sm_u + A_OFF + g * A_G_STRIDE;
    int*   s_src = (int*)(smem + IDX_OFF) + g * 64;
    int*   s_dst = s_src + 32;
    float* psum  = (float*)(smem + PSUM_OFF) + g * 64;

    // ---- stage resident B (all 512 threads) ----
    {
        const uint4* src = (const uint4*)g_wt16;
        uint4* dst = (uint4*)(smem + B_OFF);
        for (int i = tid; i < B_BYTES / 16; i += 512) dst[i] = src[i];
    }

    // ---- ldmatrix lane addressing ----
    const int li = lane & 7, lgrp = lane >> 3;
    uint32_t a_off[2]; int a_r7[2];
#pragma unroll
    for (int s = 0; s < 2; s++) {
        const int row = s * 16 + li + (lgrp & 1) * 8;
        a_off[s] = row * 128;
        a_r7[s] = row & 7;
    }
    const int a_qb = lgrp >> 1;
    uint32_t b_off[4]; int b_r7[4];
#pragma unroll
    for (int j = 0; j < 4; j++) {
        const int rn = wc * 64 + j * 16 + li + (lgrp >> 1) * 8;
        b_off[j] = rn * 128;
        b_r7[j] = rn & 7;
    }
    const int b_qb = lgrp & 1;

    const uint32_t d_off0 = row2 * 128 + (((2 * q4) ^ r7) << 4);
    const uint32_t d_off1 = row2 * 128 + (((2 * q4 + 1) ^ r7) << 4);

    // residual base: feats 0-63 in buf0 (chunk4), 64-127 in buf1 (chunk5)
    const uint32_t res_base = bA + (wc >> 1) * A_BUF_G;

    __syncthreads();   // B visible; last CTA-wide barrier

    const int t0 = blockIdx.x * NGROUP + g;
    const int tstride = gridDim.x * NGROUP;

    // ---- group prologue: first tile idx + psum, then chunk-0 gather ----
    if (t0 < NT_G) {
        const int tb0 = t0 * TILE_G;
        if (ltid < 32)       s_src[ltid] = ei[tb0 + ltid];
        else if (ltid < 64)  s_dst[ltid - 32] = ei[N_EDGES + tb0 + ltid - 32];
        else                 psum[ltid - 64] = 0.f;
    }
    GBAR(g);
    if (t0 < NT_G) {
        const char* gp = (const char*)(g_xn16 + (size_t)s_src[row2] * FD) + q4 * 32;
        cpa16(bA + d_off0, gp);
        cpa16(bA + d_off1, gp + 16);
        CP_COMMIT();
    }

    for (int t = t0; t < NT_G; t += tstride) {
        const int tb = t * TILE_G;
        const int er = tb + row2;
        const bool more = (t + tstride) < NT_G;

        float acc[2][8][4];
#pragma unroll
        for (int s = 0; s < 2; s++)
#pragma unroll
            for (int n = 0; n < 8; n++)
#pragma unroll
                for (int i = 0; i < 4; i++) acc[s][n][i] = 0.f;

        float4 ea_st[4];   // 16 f32 staged between LDG and cvt+STS

        // ---- 6 chunks of K=64 ----
        // 0=src[0:64] 1=src[64:128] 2=dst[0:64] 3=dst[64:128] (cp.async f16)
        // 4=ea[0:64]  5=ea[64:128]  (LDG f32 -> cvt -> STS, pipelined)
#pragma unroll 1
        for (int c = 0; c < 6; c++) {
            if (c < 4) CP_WAIT0();
            GBAR(g);

            if (c == 0) {
                if (ltid >= 64) psum[ltid - 64] = 0.f;
            } else if (c == 2) {
                // LDG ea chunk4 (feats 0-63) — consumed at c==3
                const float* p = ea + (size_t)er * FD + q4 * 16;
                ea_st[0] = __ldg((const float4*)p);
                ea_st[1] = __ldg((const float4*)(p + 4));
                ea_st[2] = __ldg((const float4*)(p + 8));
                ea_st[3] = __ldg((const float4*)(p + 12));
            } else if (c == 3) {
                // STS chunk4 into buf0 (free since MMA c2; GBAR ordered)
                sts16(bA + d_off0, pack8h(ea_st[0], ea_st[1]));
                sts16(bA + d_off1, pack8h(ea_st[2], ea_st[3]));
                // stage NEXT tile's indices
                if (more) {
                    const int tbn = (t + tstride) * TILE_G;
                    if (ltid < 32)      s_src[ltid] = ei[tbn + ltid];
                    else if (ltid < 64) s_dst[ltid - 32] = ei[N_EDGES + tbn + ltid - 32];
                }
                // LDG ea chunk5 (feats 64-127) — consumed at c==4
                const float* p = ea + (size_t)er * FD + 64 + q4 * 16;
                ea_st[0] = __ldg((const float4*)p);
                ea_st[1] = __ldg((const float4*)(p + 4));
                ea_st[2] = __ldg((const float4*)(p + 8));
                ea_st[3] = __ldg((const float4*)(p + 12));
            } else if (c == 4) {
                // STS chunk5 into buf1 (free since MMA c3; GBAR ordered)
                sts16(bA + A_BUF_G + d_off0, pack8h(ea_st[0], ea_st[1]));
                sts16(bA + A_BUF_G + d_off1, pack8h(ea_st[2], ea_st[3]));
            }

            // cp.async gathers for chunks 1..3
            if (c < 3) {
                const char* gp;
                if (c == 0)      gp = (const char*)(g_xn16 + (size_t)s_src[row2] * FD + 64);
                else if (c == 1) gp = (const char*)(g_xn16 + (size_t)s_dst[row2] * FD);
                else             gp = (const char*)(g_xn16 + (size_t)s_dst[row2] * FD + 64);
                const uint32_t db = bA + ((c + 1) & 1) * A_BUF_G;
                cpa16(db + d_off0, gp + q4 * 32);
                cpa16(db + d_off1, gp + q4 * 32 + 16);
                CP_COMMIT();
            }

            // MMA on chunk c (buf c&1)
            const uint32_t abuf = bA + (c & 1) * A_BUF_G;
            const uint32_t bblk = bB + c * 32768;
#pragma unroll
            for (int ks = 0; ks < 4; ks++) {
                uint32_t A[2][4];
#pragma unroll
                for (int s = 0; s < 2; s++)
                    ldsm4(A[s], abuf + a_off[s] + ((((2 * ks + a_qb) ^ a_r7[s])) << 4));
                uint32_t Bv[4][4];
#pragma unroll
                for (int j = 0; j < 4; j++)
                    ldsm4(Bv[j], bblk + b_off[j] + ((((2 * ks + b_qb) ^ b_r7[j])) << 4));
#pragma unroll
                for (int s = 0; s < 2; s++)
#pragma unroll
                    for (int j = 0; j < 4; j++) {
                        mma16816(acc[s][2 * j],     A[s], Bv[j][0], Bv[j][1]);
                        mma16816(acc[s][2 * j + 1], A[s], Bv[j][2], Bv[j][3]);
                    }
            }
        }
        // buf0 = ea feats 0-63 (f16), buf1 = feats 64-127 — residual source.

        // ---- epilogue part 1: gated residual (residual via LDS) + partials ----
        {
            float srs[4], qrs[4];
#pragma unroll
            for (int ri = 0; ri < 4; ri++) { srs[ri] = 0.f; qrs[ri] = 0.f; }

#pragma unroll
            for (int n = 0; n < 4; n++) {
                const int f = wc * 32 + n * 8 + lq * 2;
                const float2 bd = __ldg((const float2*)(bias + f));
                const float2 bg = __ldg((const float2*)(bias + 128 + f));
                const uint32_t colb = (wc & 1) * 64 + n * 16 + lq * 4;
                const uint32_t xorterm = (((colb >> 4) ^ (uint32_t)lr) << 4) + (colb & 15);
#pragma unroll
                for (int s = 0; s < 2; s++)
#pragma unroll
                    for (int rh = 0; rh < 2; rh++) {
                        const int ri = s * 2 + rh;
                        const int row = s * 16 + rh * 8 + lr;
                        uint32_t ru;
                        asm volatile("ld.shared.b32 %0, [%1];"
                                     : "=r"(ru) : "r"(res_base + row * 128 + xorterm));
                        const float2 res = __half22float2(*(__half2*)&ru);
                        float d0 = fmaxf(acc[s][n][rh * 2 + 0] + bd.x, 0.f);
                        float d1 = fmaxf(acc[s][n][rh * 2 + 1] + bd.y, 0.f);
                        float g0 = fmaxf(acc[s][n + 4][rh * 2 + 0] + bg.x, 0.f);
                        float g1 = fmaxf(acc[s][n + 4][rh * 2 + 1] + bg.y, 0.f);
                        float s0 = __frcp_rn(1.f + __expf(-g0));
                        float s1 = __frcp_rn(1.f + __expf(-g1));
                        float v0 = fmaf(d0, s0, res.x);
                        float v1 = fmaf(d1, s1, res.y);
                        acc[s][n][rh * 2 + 0] = v0;
                        acc[s][n][rh * 2 + 1] = v1;
                        srs[ri] += v0 + v1;
                        qrs[ri] = fmaf(v0, v0, fmaf(v1, v1, qrs[ri]));
                    }
            }
#pragma unroll
            for (int ri = 0; ri < 4; ri++) {
                float s_ = srs[ri], q_ = qrs[ri];
                s_ += __shfl_xor_sync(~0u, s_, 1);
                q_ += __shfl_xor_sync(~0u, q_, 1);
                s_ += __shfl_xor_sync(~0u, s_, 2);
                q_ += __shfl_xor_sync(~0u, q_, 2);
                if (lq == 0) {
                    const int row = (ri >> 1) * 16 + (ri & 1) * 8 + lr;
                    atomicAdd(&psum[row * 2],     s_);
                    atomicAdd(&psum[row * 2 + 1], q_);
                }
            }
        }
        GBAR(g);

        // ---- overlap: issue NEXT tile's chunk-0 gather (idx staged at c==3) ----
        if (more) {
            const char* gp = (const char*)(g_xn16 + (size_t)s_src[row2] * FD) + q4 * 32;
            cpa16(bA + d_off0, gp);
            cpa16(bA + d_off1, gp + 16);
            CP_COMMIT();
        }

        // ---- epilogue part 2: LayerNorm + store ----
        {
            float2 gg[4], bb[4];
#pragma unroll
            for (int n = 0; n < 4; n++) {
                const int f = wc * 32 + n * 8 + lq * 2;
                gg[n] = __ldg((const float2*)(eg + f));
                bb[n] = __ldg((const float2*)(eb + f));
            }
#pragma unroll
            for (int s = 0; s < 2; s++)
#pragma unroll
                for (int rh = 0; rh < 2; rh++) {
                    const int row = s * 16 + rh * 8 + lr;
                    const int e = tb + row;
                    const float2 p = *(const float2*)(psum + row * 2);
                    const float mu = p.x * (1.f / FD);
                    const float var = p.y * (1.f / FD) - mu * mu;
                    const float rs = rsqrtf(var + 1e-5f);
#pragma unroll
                    for (int n = 0; n < 4; n++) {
                        const int f = wc * 32 + n * 8 + lq * 2;
                        float2 o;
                        o.x = (acc[s][n][rh * 2 + 0] - mu) * rs * gg[n].x + bb[n].x;
                        o.y = (acc[s][n][rh * 2 + 1] - mu) * rs * gg[n].y + bb[n].y;
                        *(float2*)(out + (size_t)e * FD + f) = o;
                    }
                }
        }
        // next tile's c==0 GBAR orders psum reads before re-zero/atomics.
    }
}

// =====================================================================
// launch
// =====================================================================
extern "C" void kernel_launch(void* const* d_in, const int* in_sizes, int n_in,
                              void* d_out, int out_size) {
    const float* x  = (const float*)d_in[0];
    const int*   ei = (const int*)d_in[1];
    const float* ea = (const float*)d_in[2];
    const float* W  = (const float*)d_in[3];
    const float* b  = (const float*)d_in[4];
    const float* ng = (const float*)d_in[5];
    const float* nb = (const float*)d_in[6];
    const float* eg = (const float*)d_in[7];
    const float* eb = (const float*)d_in[8];
    float* out = (float*)d_out;

    prep_kernel<<<NODE_BLOCKS + NOUT, 256>>>(x, ng, nb, W);

    cudaFuncSetAttribute(edge_kernel, cudaFuncAttributeMaxDynamicSharedMemorySize, SMEM_TOTAL);
    int nsm = 148;
    cudaDeviceGetAttribute(&nsm, cudaDevAttrMultiProcessorCount, 0);
    edge_kernel<<<nsm, 512, SMEM_TOTAL>>>(ei, ea, b, eg, eb, out);
}

// round 10
// speedup vs baseline: 2.5906x; 1.0443x over previous
#include <cuda_runtime.h>
#include <cuda_fp16.h>
#include <cstdint>

// ---------------- problem constants ----------------
#define N_NODES 50000
#define N_EDGES 500000
#define FD      128
#define KDIM    384
#define NOUT    256
#define TILE_G  32                            // edges per group tile
#define NT_G    (N_EDGES / TILE_G)            // 15625 (exact)
#define NGROUP  4
#define NODE_BLOCKS ((N_NODES + 7) / 8)       // 6250

// ---------------- smem layout ----------------
#define B_OFF       0
#define B_BYTES     (6 * 32768)               // 6 K-blocks [256 n-rows x 64 halves], swizzled
#define A_OFF       B_BYTES                   // 196608
#define A_BUF_G     4096                      // one chunk [32 rows x 64 halves], swizzled
#define A_G_STRIDE  (2 * A_BUF_G)             // double buffer per group
#define IDX_OFF     (A_OFF + NGROUP * A_G_STRIDE)  // 229376 : per group src[32]+dst[32]
#define PSUM_OFF    (IDX_OFF + 1024)          // 230400 : per group 32 x (s,q) f32
#define SMEM_TOTAL  (PSUM_OFF + 1024)         // 231424 <= 232448

// ---------------- device scratch ----------------
__device__ __align__(256) __half        g_xn16[(size_t)N_NODES * FD];
__device__ __align__(256) unsigned char g_wt16[B_BYTES];

// ---------------- ptx helpers ----------------
__device__ __forceinline__ uint32_t smem_u32(const void* p) {
    uint32_t a;
    asm("{ .reg .u64 t; cvta.to.shared.u64 t, %1; cvt.u32.u64 %0, t; }" : "=r"(a) : "l"(p));
    return a;
}
__device__ __forceinline__ void cpa16(uint32_t s, const void* g) {
    asm volatile("cp.async.cg.shared.global [%0], [%1], 16;" :: "r"(s), "l"(g));
}
#define CP_COMMIT() asm volatile("cp.async.commit_group;" ::: "memory")
#define CP_WAIT0()  asm volatile("cp.async.wait_group 0;" ::: "memory")
#define GBAR(g)     asm volatile("bar.sync %0, 128;" :: "r"((g) + 1) : "memory")

__device__ __forceinline__ void ldsm4(uint32_t* r, uint32_t addr) {
    asm volatile("ldmatrix.sync.aligned.m8n8.x4.shared.b16 {%0,%1,%2,%3}, [%4];"
                 : "=r"(r[0]), "=r"(r[1]), "=r"(r[2]), "=r"(r[3]) : "r"(addr));
}
__device__ __forceinline__ void mma16816(float* c, const uint32_t* a, uint32_t b0, uint32_t b1) {
    asm volatile("mma.sync.aligned.m16n8k16.row.col.f32.f16.f16.f32 "
                 "{%0,%1,%2,%3}, {%4,%5,%6,%7}, {%8,%9}, {%0,%1,%2,%3};"
                 : "+f"(c[0]), "+f"(c[1]), "+f"(c[2]), "+f"(c[3])
                 : "r"(a[0]), "r"(a[1]), "r"(a[2]), "r"(a[3]), "r"(b0), "r"(b1));
}
__device__ __forceinline__ void sts16(uint32_t addr, uint4 v) {
    asm volatile("st.shared.v4.b32 [%0], {%1,%2,%3,%4};"
                 :: "r"(addr), "r"(v.x), "r"(v.y), "r"(v.z), "r"(v.w) : "memory");
}
__device__ __forceinline__ uint4 pack8h(float4 a, float4 b) {
    union { __half2 h[4]; uint4 u; } o;
    o.h[0] = __floats2half2_rn(a.x, a.y);
    o.h[1] = __floats2half2_rn(a.z, a.w);
    o.h[2] = __floats2half2_rn(b.x, b.y);
    o.h[3] = __floats2half2_rn(b.z, b.w);
    return o.u;
}

// =====================================================================
// prep: per-node LayerNorm -> f16, plus W convert/permute/swizzle
// =====================================================================
__global__ void prep_kernel(const float* __restrict__ x, const float* __restrict__ gma,
                            const float* __restrict__ bta, const float* __restrict__ W) {
    if (blockIdx.x < NODE_BLOCKS) {
        const int wid = threadIdx.x >> 5, lane = threadIdx.x & 31;
        const int node = blockIdx.x * 8 + wid;
        if (node >= N_NODES) return;
        float4 v = *(const float4*)(x + (size_t)node * FD + lane * 4);
        float s = v.x + v.y + v.z + v.w;
        float q = v.x * v.x + v.y * v.y + v.z * v.z + v.w * v.w;
#pragma unroll
        for (int o = 16; o; o >>= 1) {
            s += __shfl_xor_sync(~0u, s, o);
            q += __shfl_xor_sync(~0u, q, o);
        }
        const float mu = s * (1.f / FD), var = q * (1.f / FD) - mu * mu;
        const float rs = rsqrtf(var + 1e-5f);
        float4 g = *(const float4*)(gma + lane * 4);
        float4 b = *(const float4*)(bta + lane * 4);
        union { __half2 h[2]; uint2 u; } o;
        o.h[0] = __floats2half2_rn((v.x - mu) * rs * g.x + b.x, (v.y - mu) * rs * g.y + b.y);
        o.h[1] = __floats2half2_rn((v.z - mu) * rs * g.z + b.z, (v.w - mu) * rs * g.w + b.w);
        *(uint2*)(g_xn16 + (size_t)node * FD + lane * 4) = o.u;
    } else {
        // W -> Wt blocks, column-permuted: strip wc = [delta f..f+31 | gate f..f+31]
        const int n = blockIdx.x - NODE_BLOCKS;   // 0..255
        const int t = threadIdx.x;
        if (t >= KDIM / 8) return;
        const int blkN = n >> 6, j = n & 63;
        const int f = blkN * 32 + (j & 31);
        const int src = (j < 32) ? f : (128 + f);
        const int k0 = t * 8;
        const int kb = k0 >> 6, kl = k0 & 63;
        union { __half h[8]; uint4 u; } pk;
#pragma unroll
        for (int i = 0; i < 8; i++) pk.h[i] = __float2half_rn(W[(k0 + i) * NOUT + src]);
        const uint32_t phys = kb * 32768 + n * 128 + ((((kl >> 3) ^ (n & 7))) << 4);
        *(uint4*)(g_wt16 + phys) = pk.u;
    }
}

// =====================================================================
// fused edge kernel — four independent 4-warp groups per CTA,
// straight-line phase schedule, src row prefetched a full tile ahead
// =====================================================================
__global__ void __launch_bounds__(512, 1)
edge_kernel(const int* __restrict__ ei, const float* __restrict__ ea,
            const float* __restrict__ bias, const float* __restrict__ eg,
            const float* __restrict__ eb, float* __restrict__ out) {
    extern __shared__ char smem[];
    const uint32_t sm_u = smem_u32(smem);
    const uint32_t bB = sm_u + B_OFF;

    const int tid  = threadIdx.x;
    const int g    = tid >> 7;            // group 0..3
    const int ltid = tid & 127;
    const int wc   = ltid >> 5;           // 0..3 : permuted cols wc*64..+63
    const int lane = ltid & 31;
    const int row2 = ltid >> 2, q4 = ltid & 3;   // A build: 32 rows x 4 thr
    const int r7 = row2 & 7;
    const int lq = lane & 3, lr = lane >> 2;

    const uint32_t bA = sm_u + A_OFF + g * A_G_STRIDE;
    int*   s_src = (int*)(smem + IDX_OFF) + g * 64;
    int*   s_dst = s_src + 32;
    float* psum  = (float*)(smem + PSUM_OFF) + g * 64;

    // ---- stage resident B (all 512 threads) ----
    {
        const uint4* src = (const uint4*)g_wt16;
        uint4* dst = (uint4*)(smem + B_OFF);
        for (int i = tid; i < B_BYTES / 16; i += 512) dst[i] = src[i];
    }

    // ---- ldmatrix lane addressing ----
    const int li = lane & 7, lgrp = lane >> 3;
    uint32_t a_off[2]; int a_r7[2];
#pragma unroll
    for (int s = 0; s < 2; s++) {
        const int row = s * 16 + li + (lgrp & 1) * 8;
        a_off[s] = row * 128;
        a_r7[s] = row & 7;
    }
    const int a_qb = lgrp >> 1;
    uint32_t b_off[4]; int b_r7[4];
#pragma unroll
    for (int j = 0; j < 4; j++) {
        const int rn = wc * 64 + j * 16 + li + (lgrp >> 1) * 8;
        b_off[j] = rn * 128;
        b_r7[j] = rn & 7;
    }
    const int b_qb = lgrp & 1;

    const uint32_t d_off0 = row2 * 128 + (((2 * q4) ^ r7) << 4);
    const uint32_t d_off1 = row2 * 128 + (((2 * q4 + 1) ^ r7) << 4);

    // residual base: feats 0-63 in buf0 (chunk4), 64-127 in buf1 (chunk5)
    const uint32_t res_base = bA + (wc >> 1) * A_BUF_G;

    __syncthreads();   // B visible; last CTA-wide barrier

    const int t0 = blockIdx.x * NGROUP + g;
    const int tstride = gridDim.x * NGROUP;

    float acc[2][8][4];
    float4 ea_st[4];

    // MMA phase over one K=64 chunk
    auto MMAPH = [&](int c) {
        const uint32_t abuf = bA + (c & 1) * A_BUF_G;
        const uint32_t bblk = bB + c * 32768;
#pragma unroll
        for (int ks = 0; ks < 4; ks++) {
            uint32_t A[2][4];
#pragma unroll
            for (int s = 0; s < 2; s++)
                ldsm4(A[s], abuf + a_off[s] + ((((2 * ks + a_qb) ^ a_r7[s])) << 4));
            uint32_t Bv[4][4];
#pragma unroll
            for (int j = 0; j < 4; j++)
                ldsm4(Bv[j], bblk + b_off[j] + ((((2 * ks + b_qb) ^ b_r7[j])) << 4));
#pragma unroll
            for (int s = 0; s < 2; s++)
#pragma unroll
                for (int j = 0; j < 4; j++) {
                    mma16816(acc[s][2 * j],     A[s], Bv[j][0], Bv[j][1]);
                    mma16816(acc[s][2 * j + 1], A[s], Bv[j][2], Bv[j][3]);
                }
        }
    };
    // issue full 256B src-row gather into BOTH bufs (one commit group)
    auto SRC_GATHER = [&]() {
        const char* gp = (const char*)(g_xn16 + (size_t)s_src[row2] * FD) + q4 * 32;
        cpa16(bA + d_off0, gp);
        cpa16(bA + d_off1, gp + 16);
        cpa16(bA + A_BUF_G + d_off0, gp + 128);
        cpa16(bA + A_BUF_G + d_off1, gp + 144);
        CP_COMMIT();
    };

    // ---- group prologue ----
    if (t0 < NT_G) {
        const int tb0 = t0 * TILE_G;
        if (ltid < 32)       s_src[ltid] = ei[tb0 + ltid];
        else if (ltid < 64)  s_dst[ltid - 32] = ei[N_EDGES + tb0 + ltid - 32];
        else                 psum[ltid - 64] = 0.f;
    }
    GBAR(g);
    if (t0 < NT_G) SRC_GATHER();

    for (int t = t0; t < NT_G; t += tstride) {
        const int tb = t * TILE_G;
        const int er = tb + row2;
        const bool more = (t + tstride) < NT_G;

#pragma unroll
        for (int s = 0; s < 2; s++)
#pragma unroll
            for (int n = 0; n < 8; n++)
#pragma unroll
                for (int i = 0; i < 4; i++) acc[s][n][i] = 0.f;

        // ---- c0: src feats 0-63 (b0) ----
        CP_WAIT0();            // src both halves landed
        GBAR(g);               // visibility + psum/buf reuse ordering
        if (ltid >= 64) psum[ltid - 64] = 0.f;
        MMAPH(0);

        // ---- c1: src feats 64-127 (b1); prefetch dst_lo -> b0 ----
        GBAR(g);               // b0 consumed by all warps
        {
            const char* gp = (const char*)(g_xn16 + (size_t)s_dst[row2] * FD) + q4 * 32;
            cpa16(bA + d_off0, gp);
            cpa16(bA + d_off1, gp + 16);
            CP_COMMIT();
        }
        MMAPH(1);

        // ---- c2: dst feats 0-63 (b0); prefetch dst_hi -> b1; LDG ea_lo ----
        CP_WAIT0();
        GBAR(g);               // b1 consumed + dst_lo visible
        {
            const char* gp = (const char*)(g_xn16 + (size_t)s_dst[row2] * FD + 64) + q4 * 32;
            cpa16(bA + A_BUF_G + d_off0, gp);
            cpa16(bA + A_BUF_G + d_off1, gp + 16);
            CP_COMMIT();
        }
        {
            const float* p = ea + (size_t)er * FD + q4 * 16;
            ea_st[0] = __ldg((const float4*)p);
            ea_st[1] = __ldg((const float4*)(p + 4));
            ea_st[2] = __ldg((const float4*)(p + 8));
            ea_st[3] = __ldg((const float4*)(p + 12));
        }
        MMAPH(2);

        // ---- c3: dst feats 64-127 (b1); STS ea_lo -> b0; idx; LDG ea_hi ----
        CP_WAIT0();
        GBAR(g);               // b0 consumed + dst_hi visible
        sts16(bA + d_off0, pack8h(ea_st[0], ea_st[1]));
        sts16(bA + d_off1, pack8h(ea_st[2], ea_st[3]));
        if (more) {
            const int tbn = (t + tstride) * TILE_G;
            if (ltid < 32)      s_src[ltid] = ei[tbn + ltid];
            else if (ltid < 64) s_dst[ltid - 32] = ei[N_EDGES + tbn + ltid - 32];
        }
        {
            const float* p = ea + (size_t)er * FD + 64 + q4 * 16;
            ea_st[0] = __ldg((const float4*)p);
            ea_st[1] = __ldg((const float4*)(p + 4));
            ea_st[2] = __ldg((const float4*)(p + 8));
            ea_st[3] = __ldg((const float4*)(p + 12));
        }
        MMAPH(3);

        // ---- c4: ea feats 0-63 (b0); STS ea_hi -> b1 ----
        GBAR(g);               // ea_lo STS visible + b1 consumed
        sts16(bA + A_BUF_G + d_off0, pack8h(ea_st[0], ea_st[1]));
        sts16(bA + A_BUF_G + d_off1, pack8h(ea_st[2], ea_st[3]));
        MMAPH(4);

        // ---- c5: ea feats 64-127 (b1) ----
        GBAR(g);               // ea_hi STS visible
        MMAPH(5);
        // b0 = ea feats 0-63 (f16), b1 = feats 64-127 — residual source.

        // ---- epilogue part 1: gated residual (residual via LDS) + partials ----
        {
            float srs[4], qrs[4];
#pragma unroll
            for (int ri = 0; ri < 4; ri++) { srs[ri] = 0.f; qrs[ri] = 0.f; }

#pragma unroll
            for (int n = 0; n < 4; n++) {
                const int f = wc * 32 + n * 8 + lq * 2;
                const float2 bd = __ldg((const float2*)(bias + f));
                const float2 bg = __ldg((const float2*)(bias + 128 + f));
                const uint32_t colb = (wc & 1) * 64 + n * 16 + lq * 4;
                const uint32_t xorterm = (((colb >> 4) ^ (uint32_t)lr) << 4) + (colb & 15);
#pragma unroll
                for (int s = 0; s < 2; s++)
#pragma unroll
                    for (int rh = 0; rh < 2; rh++) {
                        const int ri = s * 2 + rh;
                        const int row = s * 16 + rh * 8 + lr;
                        uint32_t ru;
                        asm volatile("ld.shared.b32 %0, [%1];"
                                     : "=r"(ru) : "r"(res_base + row * 128 + xorterm));
                        const float2 res = __half22float2(*(__half2*)&ru);
                        float d0 = fmaxf(acc[s][n][rh * 2 + 0] + bd.x, 0.f);
                        float d1 = fmaxf(acc[s][n][rh * 2 + 1] + bd.y, 0.f);
                        float g0 = fmaxf(acc[s][n + 4][rh * 2 + 0] + bg.x, 0.f);
                        float g1 = fmaxf(acc[s][n + 4][rh * 2 + 1] + bg.y, 0.f);
                        float s0 = __frcp_rn(1.f + __expf(-g0));
                        float s1 = __frcp_rn(1.f + __expf(-g1));
                        float v0 = fmaf(d0, s0, res.x);
                        float v1 = fmaf(d1, s1, res.y);
                        acc[s][n][rh * 2 + 0] = v0;
                        acc[s][n][rh * 2 + 1] = v1;
                        srs[ri] += v0 + v1;
                        qrs[ri] = fmaf(v0, v0, fmaf(v1, v1, qrs[ri]));
                    }
            }
#pragma unroll
            for (int ri = 0; ri < 4; ri++) {
                float s_ = srs[ri], q_ = qrs[ri];
                s_ += __shfl_xor_sync(~0u, s_, 1);
                q_ += __shfl_xor_sync(~0u, q_, 1);
                s_ += __shfl_xor_sync(~0u, s_, 2);
                q_ += __shfl_xor_sync(~0u, q_, 2);
                if (lq == 0) {
                    const int row = (ri >> 1) * 16 + (ri & 1) * 8 + lr;
                    atomicAdd(&psum[row * 2],     s_);
                    atomicAdd(&psum[row * 2 + 1], q_);
                }
            }
        }
        GBAR(g);

        // ---- overlap: next tile's full src-row gather (both bufs free now) ----
        if (more) SRC_GATHER();

        // ---- epilogue part 2: LayerNorm + store ----
        {
            float2 gg[4], bb[4];
#pragma unroll
            for (int n = 0; n < 4; n++) {
                const int f = wc * 32 + n * 8 + lq * 2;
                gg[n] = __ldg((const float2*)(eg + f));
                bb[n] = __ldg((const float2*)(eb + f));
            }
#pragma unroll
            for (int s = 0; s < 2; s++)
#pragma unroll
                for (int rh = 0; rh < 2; rh++) {
                    const int row = s * 16 + rh * 8 + lr;
                    const int e = tb + row;
                    const float2 p = *(const float2*)(psum + row * 2);
                    const float mu = p.x * (1.f / FD);
                    const float var = p.y * (1.f / FD) - mu * mu;
                    const float rs = rsqrtf(var + 1e-5f);
#pragma unroll
                    for (int n = 0; n < 4; n++) {
                        const int f = wc * 32 + n * 8 + lq * 2;
                        float2 o;
                        o.x = (acc[s][n][rh * 2 + 0] - mu) * rs * gg[n].x + bb[n].x;
                        o.y = (acc[s][n][rh * 2 + 1] - mu) * rs * gg[n].y + bb[n].y;
                        *(float2*)(out + (size_t)e * FD + f) = o;
                    }
                }
        }
        // next tile's c0 GBAR orders psum reads before re-zero/atomics.
    }
}

// =====================================================================
// launch
// =====================================================================
extern "C" void kernel_launch(void* const* d_in, const int* in_sizes, int n_in,
                              void* d_out, int out_size) {
    const float* x  = (const float*)d_in[0];
    const int*   ei = (const int*)d_in[1];
    const float* ea = (const float*)d_in[2];
    const float* W  = (const float*)d_in[3];
    const float* b  = (const float*)d_in[4];
    const float* ng = (const float*)d_in[5];
    const float* nb = (const float*)d_in[6];
    const float* eg = (const float*)d_in[7];
    const float* eb = (const float*)d_in[8];
    float* out = (float*)d_out;

    prep_kernel<<<NODE_BLOCKS + NOUT, 256>>>(x, ng, nb, W);

    cudaFuncSetAttribute(edge_kernel, cudaFuncAttributeMaxDynamicSharedMemorySize, SMEM_TOTAL);
    int nsm = 148;
    cudaDeviceGetAttribute(&nsm, cudaDevAttrMultiProcessorCount, 0);
    edge_kernel<<<nsm, 512, SMEM_TOTAL>>>(ei, ea, b, eg, eb, out);
}